// round 1
// baseline (speedup 1.0000x reference)
#include <cuda_runtime.h>
#include <math.h>

// Problem constants
#define BATCH 4
#define SEQ   2048
#define DIM   768

// GEMM tiling
#define BM 128
#define BN 128
#define BK 8
#define TM 8
#define TN 8
#define NTHREADS 256

// Scratch buffers (allocation-free rule: __device__ globals)
__device__ float g_q[BATCH * SEQ * DIM];
__device__ float g_k[BATCH * SEQ * DIM];
__device__ float g_v[BATCH * SEQ * DIM];
__device__ float g_s[(size_t)BATCH * SEQ * SEQ];   // scores -> probabilities (in place)

// ---------------------------------------------------------------------------
// NT GEMM body: C[m,n] += sum_k A[m,k] * B[n,k]
// A: [M, lda] row-major, B: [N, ldb] row-major (both K-major along reduction).
// Tile (m0, n0), reduction over [0, kEnd), kEnd % BK == 0. No bounds checks
// (all problem dims divide the tile sizes exactly).
// ---------------------------------------------------------------------------
__device__ __forceinline__ void gemm_nt_body(
    const float* __restrict__ A, const float* __restrict__ B, float* __restrict__ C,
    int lda, int ldb, int ldc, int m0, int n0, int kEnd)
{
    __shared__ float As[BK][BM];
    __shared__ float Bs[BK][BN];

    const int tid = threadIdx.x;
    const int tx = tid & 15;     // 0..15  (N direction)
    const int ty = tid >> 4;     // 0..15  (M direction)

    float acc[TM][TN];
#pragma unroll
    for (int i = 0; i < TM; i++)
#pragma unroll
        for (int j = 0; j < TN; j++) acc[i][j] = 0.0f;

    // Load mapping: 128 rows x 8 k, each thread one float4
    const int lrow = tid >> 1;          // 0..127
    const int lk   = (tid & 1) * 4;     // 0 or 4
    const float* Aptr = A + (size_t)(m0 + lrow) * lda + lk;
    const float* Bptr = B + (size_t)(n0 + lrow) * ldb + lk;

    for (int k0 = 0; k0 < kEnd; k0 += BK) {
        float4 av = *(const float4*)(Aptr + k0);
        float4 bv = *(const float4*)(Bptr + k0);
        As[lk + 0][lrow] = av.x; As[lk + 1][lrow] = av.y;
        As[lk + 2][lrow] = av.z; As[lk + 3][lrow] = av.w;
        Bs[lk + 0][lrow] = bv.x; Bs[lk + 1][lrow] = bv.y;
        Bs[lk + 2][lrow] = bv.z; Bs[lk + 3][lrow] = bv.w;
        __syncthreads();

#pragma unroll
        for (int kk = 0; kk < BK; kk++) {
            float a[TM], b[TN];
            float4 a0 = *(const float4*)&As[kk][ty * TM];
            float4 a1 = *(const float4*)&As[kk][ty * TM + 4];
            a[0]=a0.x; a[1]=a0.y; a[2]=a0.z; a[3]=a0.w;
            a[4]=a1.x; a[5]=a1.y; a[6]=a1.z; a[7]=a1.w;
            float4 b0 = *(const float4*)&Bs[kk][tx * TN];
            float4 b1 = *(const float4*)&Bs[kk][tx * TN + 4];
            b[0]=b0.x; b[1]=b0.y; b[2]=b0.z; b[3]=b0.w;
            b[4]=b1.x; b[5]=b1.y; b[6]=b1.z; b[7]=b1.w;
#pragma unroll
            for (int i = 0; i < TM; i++)
#pragma unroll
                for (int j = 0; j < TN; j++)
                    acc[i][j] = fmaf(a[i], b[j], acc[i][j]);
        }
        __syncthreads();
    }

#pragma unroll
    for (int i = 0; i < TM; i++) {
        float* crow = C + (size_t)(m0 + ty * TM + i) * ldc + n0 + tx * TN;
        *(float4*)(crow)     = make_float4(acc[i][0], acc[i][1], acc[i][2], acc[i][3]);
        *(float4*)(crow + 4) = make_float4(acc[i][4], acc[i][5], acc[i][6], acc[i][7]);
    }
}

// ---------------------------------------------------------------------------
// NN GEMM body: C[m,n] = sum_k A[m,k] * B[k,n]
// A: [M, lda] row-major, B: [K, ldb] row-major.
// ---------------------------------------------------------------------------
__device__ __forceinline__ void gemm_nn_body(
    const float* __restrict__ A, const float* __restrict__ B, float* __restrict__ C,
    int lda, int ldb, int ldc, int m0, int n0, int kEnd)
{
    __shared__ float As[BK][BM];
    __shared__ float Bs[BK][BN];

    const int tid = threadIdx.x;
    const int tx = tid & 15;
    const int ty = tid >> 4;

    float acc[TM][TN];
#pragma unroll
    for (int i = 0; i < TM; i++)
#pragma unroll
        for (int j = 0; j < TN; j++) acc[i][j] = 0.0f;

    const int lrow = tid >> 1;          // A tile: 0..127
    const int lk   = (tid & 1) * 4;
    const float* Aptr = A + (size_t)(m0 + lrow) * lda + lk;

    const int bk = tid >> 5;            // B tile: k row 0..7
    const int bn = (tid & 31) * 4;      // n col 0..124

    for (int k0 = 0; k0 < kEnd; k0 += BK) {
        float4 av = *(const float4*)(Aptr + k0);
        float4 bv = *(const float4*)(B + (size_t)(k0 + bk) * ldb + n0 + bn);
        As[lk + 0][lrow] = av.x; As[lk + 1][lrow] = av.y;
        As[lk + 2][lrow] = av.z; As[lk + 3][lrow] = av.w;
        *(float4*)&Bs[bk][bn] = bv;
        __syncthreads();

#pragma unroll
        for (int kk = 0; kk < BK; kk++) {
            float a[TM], b[TN];
            float4 a0 = *(const float4*)&As[kk][ty * TM];
            float4 a1 = *(const float4*)&As[kk][ty * TM + 4];
            a[0]=a0.x; a[1]=a0.y; a[2]=a0.z; a[3]=a0.w;
            a[4]=a1.x; a[5]=a1.y; a[6]=a1.z; a[7]=a1.w;
            float4 b0 = *(const float4*)&Bs[kk][tx * TN];
            float4 b1 = *(const float4*)&Bs[kk][tx * TN + 4];
            b[0]=b0.x; b[1]=b0.y; b[2]=b0.z; b[3]=b0.w;
            b[4]=b1.x; b[5]=b1.y; b[6]=b1.z; b[7]=b1.w;
#pragma unroll
            for (int i = 0; i < TM; i++)
#pragma unroll
                for (int j = 0; j < TN; j++)
                    acc[i][j] = fmaf(a[i], b[j], acc[i][j]);
        }
        __syncthreads();
    }

#pragma unroll
    for (int i = 0; i < TM; i++) {
        float* crow = C + (size_t)(m0 + ty * TM + i) * ldc + n0 + tx * TN;
        *(float4*)(crow)     = make_float4(acc[i][0], acc[i][1], acc[i][2], acc[i][3]);
        *(float4*)(crow + 4) = make_float4(acc[i][4], acc[i][5], acc[i][6], acc[i][7]);
    }
}

// ---------------------------------------------------------------------------
// Kernel 1: fused QKV projection.  out[m,n] = sum_k x[m,k] * W[n,k]
// grid: (DIM/BN=6, (BATCH*SEQ)/BM=64, 3)
// ---------------------------------------------------------------------------
__global__ __launch_bounds__(NTHREADS)
void qkv_proj_kernel(const float* __restrict__ x,
                     const float* __restrict__ wq,
                     const float* __restrict__ wk,
                     const float* __restrict__ wv)
{
    const float* w;
    float* out;
    if (blockIdx.z == 0)      { w = wq; out = g_q; }
    else if (blockIdx.z == 1) { w = wk; out = g_k; }
    else                      { w = wv; out = g_v; }
    gemm_nt_body(x, w, out, DIM, DIM, DIM,
                 blockIdx.y * BM, blockIdx.x * BN, DIM);
}

// ---------------------------------------------------------------------------
// Kernel 2: raw attention scores S = Q K^T (no scale; folded into softmax).
// Skips blocks fully above the causal diagonal.
// grid: (SEQ/BN=16, SEQ/BM=16, BATCH)
// ---------------------------------------------------------------------------
__global__ __launch_bounds__(NTHREADS)
void scores_kernel()
{
    const int m0 = blockIdx.y * BM;
    const int n0 = blockIdx.x * BN;
    if (n0 > m0) return;  // entire block is masked
    const int b = blockIdx.z;
    const float* Q = g_q + (size_t)b * SEQ * DIM;
    const float* K = g_k + (size_t)b * SEQ * DIM;
    float*       S = g_s + (size_t)b * SEQ * SEQ;
    gemm_nt_body(Q, K, S, DIM, DIM, SEQ, m0, n0, DIM);
}

// ---------------------------------------------------------------------------
// Kernel 3: causal softmax in place, scale = 1/sqrt(DIM). Zeros the masked
// tail of each row so the PV GEMM needs no masking.
// grid: (SEQ, BATCH), 256 threads
// ---------------------------------------------------------------------------
__global__ __launch_bounds__(NTHREADS)
void softmax_causal_kernel()
{
    const int q = blockIdx.x;
    const int b = blockIdx.y;
    float* row = g_s + ((size_t)b * SEQ + q) * (size_t)SEQ;
    const int nvalid = q + 1;
    const float scale = 0.03608439182435161f;  // 1/sqrt(768)

    __shared__ float red[NTHREADS];
    const int tid = threadIdx.x;

    // pass 1: max
    float m = -INFINITY;
    for (int k = tid; k < nvalid; k += NTHREADS)
        m = fmaxf(m, row[k] * scale);
    red[tid] = m;
    __syncthreads();
    for (int s = NTHREADS / 2; s > 0; s >>= 1) {
        if (tid < s) red[tid] = fmaxf(red[tid], red[tid + s]);
        __syncthreads();
    }
    m = red[0];
    __syncthreads();

    // pass 2: sum of exp
    float sum = 0.0f;
    for (int k = tid; k < nvalid; k += NTHREADS)
        sum += expf(row[k] * scale - m);
    red[tid] = sum;
    __syncthreads();
    for (int s = NTHREADS / 2; s > 0; s >>= 1) {
        if (tid < s) red[tid] += red[tid + s];
        __syncthreads();
    }
    const float inv = 1.0f / red[0];
    __syncthreads();

    // pass 3: normalize + zero masked tail
    for (int k = tid; k < nvalid; k += NTHREADS)
        row[k] = expf(row[k] * scale - m) * inv;
    for (int k = nvalid + tid; k < SEQ; k += NTHREADS)
        row[k] = 0.0f;
}

// ---------------------------------------------------------------------------
// Kernel 4: O = P V.  Per q-tile, reduction only runs to kmax = m0 + BM
// (P is zero beyond the diagonal; rows above kmax were never touched).
// grid: (DIM/BN=6, SEQ/BM=16, BATCH)
// ---------------------------------------------------------------------------
__global__ __launch_bounds__(NTHREADS)
void pv_kernel(float* __restrict__ out)
{
    const int b = blockIdx.z;
    const int m0 = blockIdx.y * BM;
    const int n0 = blockIdx.x * BN;
    const float* P = g_s + (size_t)b * SEQ * SEQ;
    const float* V = g_v + (size_t)b * SEQ * DIM;
    float*       O = out + (size_t)b * SEQ * DIM;
    const int kEnd = m0 + BM;   // <= SEQ always
    gemm_nn_body(P, V, O, SEQ, DIM, DIM, m0, n0, kEnd);
}

// ---------------------------------------------------------------------------
extern "C" void kernel_launch(void* const* d_in, const int* in_sizes, int n_in,
                              void* d_out, int out_size)
{
    const float* x  = (const float*)d_in[0];
    const float* wq = (const float*)d_in[1];
    const float* wk = (const float*)d_in[2];
    const float* wv = (const float*)d_in[3];
    float* out = (float*)d_out;

    dim3 blk(NTHREADS);

    // QKV projection: M = BATCH*SEQ = 8192, N = DIM = 768
    dim3 g_proj(DIM / BN, (BATCH * SEQ) / BM, 3);
    qkv_proj_kernel<<<g_proj, blk>>>(x, wq, wk, wv);

    // Scores: per batch 16x16 tiles, causal-skipped inside
    dim3 g_sc(SEQ / BN, SEQ / BM, BATCH);
    scores_kernel<<<g_sc, blk>>>();

    // Softmax: one block per row
    dim3 g_sm(SEQ, BATCH);
    softmax_causal_kernel<<<g_sm, blk>>>();

    // PV: output GEMM
    dim3 g_pv(DIM / BN, SEQ / BM, BATCH);
    pv_kernel<<<g_pv, blk>>>(out);
}

// round 4
// speedup vs baseline: 3.1601x; 3.1601x over previous
#include <cuda_runtime.h>
#include <cuda_bf16.h>
#include <math.h>
#include <stdint.h>

// ---------------------------------------------------------------------------
// Problem constants
// ---------------------------------------------------------------------------
#define BATCH 4
#define SEQ   2048
#define DIM   768
#define NTOK  (BATCH * SEQ)          // 8192
#define NTHREADS 256

// Tiling: 128x128 CTA tile, K chunk of 64 bf16 (rows are 128B -> SW128 swizzle)
#define BK 64
#define TILE_B  16384                // 128 rows * 128 bytes
#define STAGE_B (4 * TILE_B)         // A_hi, A_lo, B_hi, B_lo
#define SMEM_BYTES (2 * STAGE_B)     // double buffered = 128 KB

#define SWZ(o) ((o) ^ ((((uint32_t)(o)) >> 3) & 0x70))

// ---------------------------------------------------------------------------
// Scratch (__device__ globals: allocation-free rule).
// NOTE: these are ONLY referenced from device code — never passed as kernel
// arguments from host (host-side symbol address is invalid on device).
// ---------------------------------------------------------------------------
__device__ __align__(128) __nv_bfloat16 g_xh[NTOK * DIM], g_xl[NTOK * DIM];
__device__ __align__(128) __nv_bfloat16 g_wqh[DIM * DIM], g_wql[DIM * DIM];
__device__ __align__(128) __nv_bfloat16 g_wkh[DIM * DIM], g_wkl[DIM * DIM];
__device__ __align__(128) __nv_bfloat16 g_wvh[DIM * DIM], g_wvl[DIM * DIM];
__device__ __align__(128) __nv_bfloat16 g_qh[NTOK * DIM], g_ql[NTOK * DIM];
__device__ __align__(128) __nv_bfloat16 g_kh[NTOK * DIM], g_kl[NTOK * DIM];
__device__ __align__(128) __nv_bfloat16 g_vth[DIM * NTOK], g_vtl[DIM * NTOK]; // V^T
__device__ __align__(128) float         g_s[(size_t)BATCH * SEQ * SEQ];
__device__ __align__(128) __nv_bfloat16 g_ph[(size_t)BATCH * SEQ * SEQ];
__device__ __align__(128) __nv_bfloat16 g_pl[(size_t)BATCH * SEQ * SEQ];

// ---------------------------------------------------------------------------
// PTX helpers (plain compute_80-class: no 'a'-feature instructions)
// ---------------------------------------------------------------------------
__device__ __forceinline__ uint32_t smem_u32(const void* p) {
    uint32_t a;
    asm("{ .reg .u64 t; cvta.to.shared.u64 t, %1; cvt.u32.u64 %0, t; }"
        : "=r"(a) : "l"(p));
    return a;
}
__device__ __forceinline__ void cp16(uint32_t dst, const void* src) {
    asm volatile("cp.async.cg.shared.global [%0], [%1], 16;"
                 :: "r"(dst), "l"(src));
}
__device__ __forceinline__ void cp_commit() {
    asm volatile("cp.async.commit_group;" ::: "memory");
}
template <int N>
__device__ __forceinline__ void cp_wait() {
    asm volatile("cp.async.wait_group %0;" :: "n"(N) : "memory");
}
__device__ __forceinline__ void ldsm4(uint32_t addr, uint32_t* r) {
    asm volatile("ldmatrix.sync.aligned.m8n8.x4.shared.b16 {%0,%1,%2,%3}, [%4];"
                 : "=r"(r[0]), "=r"(r[1]), "=r"(r[2]), "=r"(r[3]) : "r"(addr));
}
__device__ __forceinline__ void ldsm2(uint32_t addr, uint32_t* r) {
    asm volatile("ldmatrix.sync.aligned.m8n8.x2.shared.b16 {%0,%1}, [%2];"
                 : "=r"(r[0]), "=r"(r[1]) : "r"(addr));
}
__device__ __forceinline__ void mma16816(float* d, const uint32_t* a, const uint32_t* b) {
    asm volatile(
        "mma.sync.aligned.m16n8k16.row.col.f32.bf16.bf16.f32 "
        "{%0,%1,%2,%3}, {%4,%5,%6,%7}, {%8,%9}, {%0,%1,%2,%3};"
        : "+f"(d[0]), "+f"(d[1]), "+f"(d[2]), "+f"(d[3])
        : "r"(a[0]), "r"(a[1]), "r"(a[2]), "r"(a[3]), "r"(b[0]), "r"(b[1]));
}

// ---------------------------------------------------------------------------
// 128x128 NT GEMM tile, split-bf16 3-term: D ~= (Ah+Al)(Bh+Bl)^T  (drop Al*Bl)
// EPI 0: write bf16 hi/lo pair.  EPI 1: write fp32.
// 256 threads = 8 warps (2 x 4), warp tile 64 x 32.
// ---------------------------------------------------------------------------
template <int EPI>
__device__ __forceinline__ void gemm_core(
    const __nv_bfloat16* __restrict__ Ah, const __nv_bfloat16* __restrict__ Al, int lda,
    const __nv_bfloat16* __restrict__ Bh, const __nv_bfloat16* __restrict__ Bl, int ldb,
    int m0, int n0, int nIter,
    __nv_bfloat16* __restrict__ Oh, __nv_bfloat16* __restrict__ Ol,
    float* __restrict__ Of, int ldc)
{
    extern __shared__ char smem[];
    const uint32_t sbase = smem_u32(smem);
    const int tid  = threadIdx.x;
    const int lane = tid & 31;
    const int wid  = tid >> 5;
    const int wm   = wid >> 2;   // 0..1 : rows wm*64
    const int wn   = wid & 3;    // 0..3 : cols wn*32

    const __nv_bfloat16* A0h = Ah + (size_t)m0 * lda;
    const __nv_bfloat16* A0l = Al + (size_t)m0 * lda;
    const __nv_bfloat16* B0h = Bh + (size_t)n0 * ldb;
    const __nv_bfloat16* B0l = Bl + (size_t)n0 * ldb;

    auto load_tile = [&](int it) {
        const uint32_t db = sbase + (uint32_t)(it & 1) * STAGE_B;
        const int k0 = it * BK;
#pragma unroll
        for (int i = 0; i < 4; i++) {
            const int c = tid + i * NTHREADS;       // 0..1023
            const int row = c >> 3, ch = c & 7;
            const uint32_t so = SWZ((uint32_t)(row * 128 + ch * 16));
            const size_t ga = (size_t)row * lda + k0 + ch * 8;
            const size_t gb = (size_t)row * ldb + k0 + ch * 8;
            cp16(db + so,              A0h + ga);
            cp16(db + TILE_B + so,     A0l + ga);
            cp16(db + 2 * TILE_B + so, B0h + gb);
            cp16(db + 3 * TILE_B + so, B0l + gb);
        }
        cp_commit();
    };

    float acc[4][4][4];
#pragma unroll
    for (int i = 0; i < 4; i++)
#pragma unroll
        for (int j = 0; j < 4; j++)
#pragma unroll
            for (int v = 0; v < 4; v++) acc[i][j][v] = 0.0f;

    // per-lane ldmatrix address components (byte offsets, pre-swizzle)
    const uint32_t a_l = ((uint32_t)(lane & 15) << 7) + ((uint32_t)(lane >> 4) << 4);
    const uint32_t b_l = ((uint32_t)(lane & 7) << 7) + ((uint32_t)((lane >> 3) & 1) << 4);

    load_tile(0);
    if (nIter > 1) load_tile(1);

    for (int it = 0; it < nIter; ++it) {
        if (it + 1 < nIter) cp_wait<1>(); else cp_wait<0>();
        __syncthreads();

        const uint32_t db = sbase + (uint32_t)(it & 1) * STAGE_B;
#pragma unroll
        for (int ks = 0; ks < 4; ks++) {
            uint32_t ah[4][4], al_[4][4], bh[4][2], bl_[4][2];
#pragma unroll
            for (int fm = 0; fm < 4; fm++) {
                const uint32_t sw = SWZ(((uint32_t)(wm * 64 + fm * 16) << 7) +
                                        (uint32_t)(ks * 32) + a_l);
                ldsm4(db + sw, ah[fm]);
                ldsm4(db + TILE_B + sw, al_[fm]);
            }
#pragma unroll
            for (int fn = 0; fn < 4; fn++) {
                const uint32_t sw = SWZ(((uint32_t)(wn * 32 + fn * 8) << 7) +
                                        (uint32_t)(ks * 32) + b_l);
                ldsm2(db + 2 * TILE_B + sw, bh[fn]);
                ldsm2(db + 3 * TILE_B + sw, bl_[fn]);
            }
#pragma unroll
            for (int fm = 0; fm < 4; fm++)
#pragma unroll
                for (int fn = 0; fn < 4; fn++)
                    mma16816(acc[fm][fn], ah[fm], bh[fn]);
#pragma unroll
            for (int fm = 0; fm < 4; fm++)
#pragma unroll
                for (int fn = 0; fn < 4; fn++)
                    mma16816(acc[fm][fn], ah[fm], bl_[fn]);
#pragma unroll
            for (int fm = 0; fm < 4; fm++)
#pragma unroll
                for (int fn = 0; fn < 4; fn++)
                    mma16816(acc[fm][fn], al_[fm], bh[fn]);
        }
        __syncthreads();
        if (it + 2 < nIter) load_tile(it + 2);
    }

    // Epilogue from register accumulators
    const int er = lane >> 2;            // 0..7
    const int ec = (lane & 3) * 2;
#pragma unroll
    for (int fm = 0; fm < 4; fm++) {
#pragma unroll
        for (int fn = 0; fn < 4; fn++) {
            const int r0 = m0 + wm * 64 + fm * 16 + er;
            const int r1 = r0 + 8;
            const int c  = n0 + wn * 32 + fn * 8 + ec;
            if (EPI == 1) {
                float2 v0 = make_float2(acc[fm][fn][0], acc[fm][fn][1]);
                float2 v1 = make_float2(acc[fm][fn][2], acc[fm][fn][3]);
                *(float2*)(Of + (size_t)r0 * ldc + c) = v0;
                *(float2*)(Of + (size_t)r1 * ldc + c) = v1;
            } else {
#pragma unroll
                for (int p = 0; p < 2; p++) {
                    const int rr = p == 0 ? r0 : r1;
                    const float f0 = acc[fm][fn][2 * p];
                    const float f1 = acc[fm][fn][2 * p + 1];
                    const __nv_bfloat16 h0 = __float2bfloat16(f0);
                    const __nv_bfloat16 h1 = __float2bfloat16(f1);
                    __nv_bfloat162 hv; hv.x = h0; hv.y = h1;
                    __nv_bfloat162 lv;
                    lv.x = __float2bfloat16(f0 - __bfloat162float(h0));
                    lv.y = __float2bfloat16(f1 - __bfloat162float(h1));
                    *(__nv_bfloat162*)(Oh + (size_t)rr * ldc + c) = hv;
                    *(__nv_bfloat162*)(Ol + (size_t)rr * ldc + c) = lv;
                }
            }
        }
    }
}

// ---------------------------------------------------------------------------
// Kernel 0: fused fp32 -> bf16 hi/lo split for x, wq, wk, wv.
// Destination globals selected IN DEVICE CODE (fix for round-3 bug).
// ---------------------------------------------------------------------------
#define NX4 (NTOK * DIM / 4)
#define NW4 (DIM * DIM / 4)

__global__ __launch_bounds__(NTHREADS)
void convert_all_kernel(const float* __restrict__ x,  const float* __restrict__ wq,
                        const float* __restrict__ wk, const float* __restrict__ wv)
{
    const int i = blockIdx.x * NTHREADS + threadIdx.x;
    const float* src;
    __nv_bfloat16 *hi, *lo;
    int j;
    if (i < NX4)                  { src = x;  hi = g_xh;  lo = g_xl;  j = i; }
    else if (i < NX4 + NW4)       { src = wq; hi = g_wqh; lo = g_wql; j = i - NX4; }
    else if (i < NX4 + 2 * NW4)   { src = wk; hi = g_wkh; lo = g_wkl; j = i - NX4 - NW4; }
    else if (i < NX4 + 3 * NW4)   { src = wv; hi = g_wvh; lo = g_wvl; j = i - NX4 - 2 * NW4; }
    else return;

    const float4 v = ((const float4*)src)[j];
    const __nv_bfloat16 h0 = __float2bfloat16(v.x), h1 = __float2bfloat16(v.y);
    const __nv_bfloat16 h2 = __float2bfloat16(v.z), h3 = __float2bfloat16(v.w);
    __nv_bfloat162 hv0, hv1, lv0, lv1;
    hv0.x = h0; hv0.y = h1; hv1.x = h2; hv1.y = h3;
    lv0.x = __float2bfloat16(v.x - __bfloat162float(h0));
    lv0.y = __float2bfloat16(v.y - __bfloat162float(h1));
    lv1.x = __float2bfloat16(v.z - __bfloat162float(h2));
    lv1.y = __float2bfloat16(v.w - __bfloat162float(h3));
    ((__nv_bfloat162*)hi)[2 * j]     = hv0;
    ((__nv_bfloat162*)hi)[2 * j + 1] = hv1;
    ((__nv_bfloat162*)lo)[2 * j]     = lv0;
    ((__nv_bfloat162*)lo)[2 * j + 1] = lv1;
}

// ---------------------------------------------------------------------------
// Kernel 1: fused QKV. z=0: Q = X Wq^T, z=1: K = X Wk^T, z=2: V^T = Wv X^T
// ---------------------------------------------------------------------------
__global__ __launch_bounds__(NTHREADS)
void qkv_kernel()
{
    const int z = blockIdx.z;
    if (z == 0) {
        gemm_core<0>(g_xh, g_xl, DIM, g_wqh, g_wql, DIM,
                     blockIdx.y * 128, blockIdx.x * 128, DIM / BK,
                     g_qh, g_ql, nullptr, DIM);
    } else if (z == 1) {
        gemm_core<0>(g_xh, g_xl, DIM, g_wkh, g_wkl, DIM,
                     blockIdx.y * 128, blockIdx.x * 128, DIM / BK,
                     g_kh, g_kl, nullptr, DIM);
    } else {
        gemm_core<0>(g_wvh, g_wvl, DIM, g_xh, g_xl, DIM,
                     blockIdx.x * 128, blockIdx.y * 128, DIM / BK,
                     g_vth, g_vtl, nullptr, NTOK);
    }
}

// ---------------------------------------------------------------------------
// Kernel 2: scores S = Q K^T (fp32 out), causal block skip
// ---------------------------------------------------------------------------
__global__ __launch_bounds__(NTHREADS)
void scores_kernel()
{
    const int m0 = blockIdx.y * 128, n0 = blockIdx.x * 128;
    if (n0 > m0) return;
    const int b = blockIdx.z;
    const size_t qo = (size_t)b * SEQ * DIM;
    gemm_core<1>(g_qh + qo, g_ql + qo, DIM,
                 g_kh + qo, g_kl + qo, DIM,
                 m0, n0, DIM / BK,
                 nullptr, nullptr, g_s + (size_t)b * SEQ * SEQ, SEQ);
}

// ---------------------------------------------------------------------------
// Kernel 3: causal softmax, fp32 in, bf16 hi/lo out, zeroed tails
// ---------------------------------------------------------------------------
__global__ __launch_bounds__(NTHREADS)
void softmax_kernel()
{
    const int q = blockIdx.x, b = blockIdx.y;
    const float* row = g_s + ((size_t)b * SEQ + q) * SEQ;
    __nv_bfloat16* ph = g_ph + ((size_t)b * SEQ + q) * SEQ;
    __nv_bfloat16* pl = g_pl + ((size_t)b * SEQ + q) * SEQ;
    const int nvalid = q + 1;
    const float scale = 0.03608439182435161f;  // 1/sqrt(768)

    __shared__ float red[NTHREADS];
    const int tid = threadIdx.x;

    float mx = -INFINITY;
    for (int k = tid; k < nvalid; k += NTHREADS) mx = fmaxf(mx, row[k]);
    red[tid] = mx;
    __syncthreads();
    for (int s = NTHREADS / 2; s > 0; s >>= 1) {
        if (tid < s) red[tid] = fmaxf(red[tid], red[tid + s]);
        __syncthreads();
    }
    mx = red[0];
    __syncthreads();

    float sum = 0.0f;
    for (int k = tid; k < nvalid; k += NTHREADS)
        sum += expf((row[k] - mx) * scale);
    red[tid] = sum;
    __syncthreads();
    for (int s = NTHREADS / 2; s > 0; s >>= 1) {
        if (tid < s) red[tid] += red[tid + s];
        __syncthreads();
    }
    const float inv = 1.0f / red[0];
    __syncthreads();

    for (int k2 = tid; k2 < SEQ / 2; k2 += NTHREADS) {
        const int k = 2 * k2;
        float p0 = 0.0f, p1 = 0.0f;
        if (k < nvalid)     p0 = expf((row[k] - mx) * scale) * inv;
        if (k + 1 < nvalid) p1 = expf((row[k + 1] - mx) * scale) * inv;
        const __nv_bfloat16 h0 = __float2bfloat16(p0);
        const __nv_bfloat16 h1 = __float2bfloat16(p1);
        __nv_bfloat162 hv; hv.x = h0; hv.y = h1;
        __nv_bfloat162 lv;
        lv.x = __float2bfloat16(p0 - __bfloat162float(h0));
        lv.y = __float2bfloat16(p1 - __bfloat162float(h1));
        *(__nv_bfloat162*)(ph + k) = hv;
        *(__nv_bfloat162*)(pl + k) = lv;
    }
}

// ---------------------------------------------------------------------------
// Kernel 4: O = P V via V^T (NT GEMM), k bounded by the causal diagonal
// ---------------------------------------------------------------------------
__global__ __launch_bounds__(NTHREADS)
void pv_kernel(float* __restrict__ out)
{
    const int b = blockIdx.z;
    const int m0 = blockIdx.y * 128, n0 = blockIdx.x * 128;
    gemm_core<1>(g_ph + (size_t)b * SEQ * SEQ, g_pl + (size_t)b * SEQ * SEQ, SEQ,
                 g_vth + (size_t)b * SEQ, g_vtl + (size_t)b * SEQ, NTOK,
                 m0, n0, (m0 + 128) / BK,
                 nullptr, nullptr, out + (size_t)b * SEQ * DIM, DIM);
}

// ---------------------------------------------------------------------------
extern "C" void kernel_launch(void* const* d_in, const int* in_sizes, int n_in,
                              void* d_out, int out_size)
{
    const float* x  = (const float*)d_in[0];
    const float* wq = (const float*)d_in[1];
    const float* wk = (const float*)d_in[2];
    const float* wv = (const float*)d_in[3];
    float* out = (float*)d_out;

    cudaFuncSetAttribute(qkv_kernel,    cudaFuncAttributeMaxDynamicSharedMemorySize, SMEM_BYTES);
    cudaFuncSetAttribute(scores_kernel, cudaFuncAttributeMaxDynamicSharedMemorySize, SMEM_BYTES);
    cudaFuncSetAttribute(pv_kernel,     cudaFuncAttributeMaxDynamicSharedMemorySize, SMEM_BYTES);

    const int ntot = NX4 + 3 * NW4;
    convert_all_kernel<<<(ntot + NTHREADS - 1) / NTHREADS, NTHREADS>>>(x, wq, wk, wv);

    qkv_kernel<<<dim3(DIM / 128, NTOK / 128, 3), NTHREADS, SMEM_BYTES>>>();
    scores_kernel<<<dim3(SEQ / 128, SEQ / 128, BATCH), NTHREADS, SMEM_BYTES>>>();
    softmax_kernel<<<dim3(SEQ, BATCH), NTHREADS>>>();
    pv_kernel<<<dim3(DIM / 128, SEQ / 128, BATCH), NTHREADS, SMEM_BYTES>>>(out);
}

// round 5
// speedup vs baseline: 3.3431x; 1.0579x over previous
#include <cuda_runtime.h>
#include <cuda_bf16.h>
#include <math.h>
#include <stdint.h>

// ---------------------------------------------------------------------------
// Problem constants
// ---------------------------------------------------------------------------
#define BATCH 4
#define SEQ   2048
#define DIM   768
#define NTOK  (BATCH * SEQ)          // 8192
#define NTHREADS 256
#define SCALE 0.03608439182435161f   // 1/sqrt(768)

// bf16 GEMM tiling: 128x128 CTA tile, K chunk of 64 bf16 (128B rows, SW128)
#define BK 64
#define TILE_B  16384
#define STAGE_B (4 * TILE_B)
#define SMEM_BYTES (2 * STAGE_B)     // 128 KB

// tf32 PV tiling: 128x128 CTA tile, K chunk of 32 fp32 (128B rows, SW128)
#define BK2 32
#define PV_TILE_B  16384
#define PV_STAGE_B (2 * PV_TILE_B)
#define PV_SMEM    (2 * PV_STAGE_B)  // 64 KB -> 2 CTAs/SM

#define SWZ(o) ((o) ^ ((((uint32_t)(o)) >> 3) & 0x70))

// ---------------------------------------------------------------------------
// Scratch (__device__ globals; referenced ONLY from device code)
// ---------------------------------------------------------------------------
__device__ __align__(128) __nv_bfloat16 g_xh[NTOK * DIM], g_xl[NTOK * DIM];
__device__ __align__(128) __nv_bfloat16 g_wqh[DIM * DIM], g_wql[DIM * DIM];
__device__ __align__(128) __nv_bfloat16 g_wkh[DIM * DIM], g_wkl[DIM * DIM];
__device__ __align__(128) __nv_bfloat16 g_wvh[DIM * DIM], g_wvl[DIM * DIM];
__device__ __align__(128) __nv_bfloat16 g_qh[NTOK * DIM], g_ql[NTOK * DIM];
__device__ __align__(128) __nv_bfloat16 g_kh[NTOK * DIM], g_kl[NTOK * DIM];
__device__ __align__(128) float         g_vt[DIM * NTOK];   // V^T fp32 (tf32-rounded)
__device__ __align__(128) float         g_s[(size_t)BATCH * SEQ * SEQ]; // S -> P in place

// ---------------------------------------------------------------------------
// PTX helpers (plain compute_80-class)
// ---------------------------------------------------------------------------
__device__ __forceinline__ uint32_t smem_u32(const void* p) {
    uint32_t a;
    asm("{ .reg .u64 t; cvta.to.shared.u64 t, %1; cvt.u32.u64 %0, t; }"
        : "=r"(a) : "l"(p));
    return a;
}
__device__ __forceinline__ void cp16(uint32_t dst, const void* src) {
    asm volatile("cp.async.cg.shared.global [%0], [%1], 16;" :: "r"(dst), "l"(src));
}
__device__ __forceinline__ void cp_commit() {
    asm volatile("cp.async.commit_group;" ::: "memory");
}
template <int N>
__device__ __forceinline__ void cp_wait() {
    asm volatile("cp.async.wait_group %0;" :: "n"(N) : "memory");
}
__device__ __forceinline__ void ldsm4(uint32_t addr, uint32_t* r) {
    asm volatile("ldmatrix.sync.aligned.m8n8.x4.shared.b16 {%0,%1,%2,%3}, [%4];"
                 : "=r"(r[0]), "=r"(r[1]), "=r"(r[2]), "=r"(r[3]) : "r"(addr));
}
__device__ __forceinline__ void ldsm2(uint32_t addr, uint32_t* r) {
    asm volatile("ldmatrix.sync.aligned.m8n8.x2.shared.b16 {%0,%1}, [%2];"
                 : "=r"(r[0]), "=r"(r[1]) : "r"(addr));
}
__device__ __forceinline__ void mma16816(float* d, const uint32_t* a, const uint32_t* b) {
    asm volatile(
        "mma.sync.aligned.m16n8k16.row.col.f32.bf16.bf16.f32 "
        "{%0,%1,%2,%3}, {%4,%5,%6,%7}, {%8,%9}, {%0,%1,%2,%3};"
        : "+f"(d[0]), "+f"(d[1]), "+f"(d[2]), "+f"(d[3])
        : "r"(a[0]), "r"(a[1]), "r"(a[2]), "r"(a[3]), "r"(b[0]), "r"(b[1]));
}
__device__ __forceinline__ void mma1688t(float* d, const uint32_t* a, const uint32_t* b) {
    asm volatile(
        "mma.sync.aligned.m16n8k8.row.col.f32.tf32.tf32.f32 "
        "{%0,%1,%2,%3}, {%4,%5,%6,%7}, {%8,%9}, {%0,%1,%2,%3};"
        : "+f"(d[0]), "+f"(d[1]), "+f"(d[2]), "+f"(d[3])
        : "r"(a[0]), "r"(a[1]), "r"(a[2]), "r"(a[3]), "r"(b[0]), "r"(b[1]));
}
__device__ __forceinline__ uint32_t lds32(uint32_t addr) {
    uint32_t v;
    asm volatile("ld.shared.b32 %0, [%1];" : "=r"(v) : "r"(addr));
    return v;
}
__device__ __forceinline__ float to_tf32(float x) {
    float r;
    asm("cvt.rna.tf32.f32 %0, %1;" : "=f"(r) : "f"(x));
    return r;
}

// ---------------------------------------------------------------------------
// 128x128 NT GEMM tile, split-bf16 3-term: D ~= (Ah+Al)(Bh+Bl)^T  (drop Al*Bl)
// EPI 0: bf16 hi/lo pair.  EPI 1: fp32.  EPI 2: fp32 tf32-rounded.
// 256 threads = 8 warps (2x4), warp tile 64x32.
// ---------------------------------------------------------------------------
template <int EPI>
__device__ __forceinline__ void gemm_core(
    const __nv_bfloat16* __restrict__ Ah, const __nv_bfloat16* __restrict__ Al, int lda,
    const __nv_bfloat16* __restrict__ Bh, const __nv_bfloat16* __restrict__ Bl, int ldb,
    int m0, int n0, int nIter,
    __nv_bfloat16* __restrict__ Oh, __nv_bfloat16* __restrict__ Ol,
    float* __restrict__ Of, int ldc)
{
    extern __shared__ char smem[];
    const uint32_t sbase = smem_u32(smem);
    const int tid  = threadIdx.x;
    const int lane = tid & 31;
    const int wid  = tid >> 5;
    const int wm   = wid >> 2;
    const int wn   = wid & 3;

    const __nv_bfloat16* A0h = Ah + (size_t)m0 * lda;
    const __nv_bfloat16* A0l = Al + (size_t)m0 * lda;
    const __nv_bfloat16* B0h = Bh + (size_t)n0 * ldb;
    const __nv_bfloat16* B0l = Bl + (size_t)n0 * ldb;

    auto load_tile = [&](int it) {
        const uint32_t db = sbase + (uint32_t)(it & 1) * STAGE_B;
        const int k0 = it * BK;
#pragma unroll
        for (int i = 0; i < 4; i++) {
            const int c = tid + i * NTHREADS;
            const int row = c >> 3, ch = c & 7;
            const uint32_t so = SWZ((uint32_t)(row * 128 + ch * 16));
            const size_t ga = (size_t)row * lda + k0 + ch * 8;
            const size_t gb = (size_t)row * ldb + k0 + ch * 8;
            cp16(db + so,              A0h + ga);
            cp16(db + TILE_B + so,     A0l + ga);
            cp16(db + 2 * TILE_B + so, B0h + gb);
            cp16(db + 3 * TILE_B + so, B0l + gb);
        }
        cp_commit();
    };

    float acc[4][4][4];
#pragma unroll
    for (int i = 0; i < 4; i++)
#pragma unroll
        for (int j = 0; j < 4; j++)
#pragma unroll
            for (int v = 0; v < 4; v++) acc[i][j][v] = 0.0f;

    const uint32_t a_l = ((uint32_t)(lane & 15) << 7) + ((uint32_t)(lane >> 4) << 4);
    const uint32_t b_l = ((uint32_t)(lane & 7) << 7) + ((uint32_t)((lane >> 3) & 1) << 4);

    load_tile(0);
    if (nIter > 1) load_tile(1);

    for (int it = 0; it < nIter; ++it) {
        if (it + 1 < nIter) cp_wait<1>(); else cp_wait<0>();
        __syncthreads();

        const uint32_t db = sbase + (uint32_t)(it & 1) * STAGE_B;
#pragma unroll
        for (int ks = 0; ks < 4; ks++) {
            uint32_t ah[4][4], al_[4][4], bh[4][2], bl_[4][2];
#pragma unroll
            for (int fm = 0; fm < 4; fm++) {
                const uint32_t sw = SWZ(((uint32_t)(wm * 64 + fm * 16) << 7) +
                                        (uint32_t)(ks * 32) + a_l);
                ldsm4(db + sw, ah[fm]);
                ldsm4(db + TILE_B + sw, al_[fm]);
            }
#pragma unroll
            for (int fn = 0; fn < 4; fn++) {
                const uint32_t sw = SWZ(((uint32_t)(wn * 32 + fn * 8) << 7) +
                                        (uint32_t)(ks * 32) + b_l);
                ldsm2(db + 2 * TILE_B + sw, bh[fn]);
                ldsm2(db + 3 * TILE_B + sw, bl_[fn]);
            }
#pragma unroll
            for (int fm = 0; fm < 4; fm++)
#pragma unroll
                for (int fn = 0; fn < 4; fn++)
                    mma16816(acc[fm][fn], ah[fm], bh[fn]);
#pragma unroll
            for (int fm = 0; fm < 4; fm++)
#pragma unroll
                for (int fn = 0; fn < 4; fn++)
                    mma16816(acc[fm][fn], ah[fm], bl_[fn]);
#pragma unroll
            for (int fm = 0; fm < 4; fm++)
#pragma unroll
                for (int fn = 0; fn < 4; fn++)
                    mma16816(acc[fm][fn], al_[fm], bh[fn]);
        }
        __syncthreads();
        if (it + 2 < nIter) load_tile(it + 2);
    }

    const int er = lane >> 2;
    const int ec = (lane & 3) * 2;
#pragma unroll
    for (int fm = 0; fm < 4; fm++) {
#pragma unroll
        for (int fn = 0; fn < 4; fn++) {
            const int r0 = m0 + wm * 64 + fm * 16 + er;
            const int r1 = r0 + 8;
            const int c  = n0 + wn * 32 + fn * 8 + ec;
            if (EPI == 1) {
                *(float2*)(Of + (size_t)r0 * ldc + c) = make_float2(acc[fm][fn][0], acc[fm][fn][1]);
                *(float2*)(Of + (size_t)r1 * ldc + c) = make_float2(acc[fm][fn][2], acc[fm][fn][3]);
            } else if (EPI == 2) {
                *(float2*)(Of + (size_t)r0 * ldc + c) =
                    make_float2(to_tf32(acc[fm][fn][0]), to_tf32(acc[fm][fn][1]));
                *(float2*)(Of + (size_t)r1 * ldc + c) =
                    make_float2(to_tf32(acc[fm][fn][2]), to_tf32(acc[fm][fn][3]));
            } else {
#pragma unroll
                for (int p = 0; p < 2; p++) {
                    const int rr = p == 0 ? r0 : r1;
                    const float f0 = acc[fm][fn][2 * p];
                    const float f1 = acc[fm][fn][2 * p + 1];
                    const __nv_bfloat16 h0 = __float2bfloat16(f0);
                    const __nv_bfloat16 h1 = __float2bfloat16(f1);
                    __nv_bfloat162 hv; hv.x = h0; hv.y = h1;
                    __nv_bfloat162 lv;
                    lv.x = __float2bfloat16(f0 - __bfloat162float(h0));
                    lv.y = __float2bfloat16(f1 - __bfloat162float(h1));
                    *(__nv_bfloat162*)(Oh + (size_t)rr * ldc + c) = hv;
                    *(__nv_bfloat162*)(Ol + (size_t)rr * ldc + c) = lv;
                }
            }
        }
    }
}

// ---------------------------------------------------------------------------
// Kernel 0: fused fp32 -> bf16 hi/lo split (device-side global selection)
// ---------------------------------------------------------------------------
#define NX4 (NTOK * DIM / 4)
#define NW4 (DIM * DIM / 4)

__global__ __launch_bounds__(NTHREADS)
void convert_all_kernel(const float* __restrict__ x,  const float* __restrict__ wq,
                        const float* __restrict__ wk, const float* __restrict__ wv)
{
    const int i = blockIdx.x * NTHREADS + threadIdx.x;
    const float* src;
    __nv_bfloat16 *hi, *lo;
    int j;
    if (i < NX4)                  { src = x;  hi = g_xh;  lo = g_xl;  j = i; }
    else if (i < NX4 + NW4)       { src = wq; hi = g_wqh; lo = g_wql; j = i - NX4; }
    else if (i < NX4 + 2 * NW4)   { src = wk; hi = g_wkh; lo = g_wkl; j = i - NX4 - NW4; }
    else if (i < NX4 + 3 * NW4)   { src = wv; hi = g_wvh; lo = g_wvl; j = i - NX4 - 2 * NW4; }
    else return;

    const float4 v = ((const float4*)src)[j];
    const __nv_bfloat16 h0 = __float2bfloat16(v.x), h1 = __float2bfloat16(v.y);
    const __nv_bfloat16 h2 = __float2bfloat16(v.z), h3 = __float2bfloat16(v.w);
    __nv_bfloat162 hv0, hv1, lv0, lv1;
    hv0.x = h0; hv0.y = h1; hv1.x = h2; hv1.y = h3;
    lv0.x = __float2bfloat16(v.x - __bfloat162float(h0));
    lv0.y = __float2bfloat16(v.y - __bfloat162float(h1));
    lv1.x = __float2bfloat16(v.z - __bfloat162float(h2));
    lv1.y = __float2bfloat16(v.w - __bfloat162float(h3));
    ((__nv_bfloat162*)hi)[2 * j]     = hv0;
    ((__nv_bfloat162*)hi)[2 * j + 1] = hv1;
    ((__nv_bfloat162*)lo)[2 * j]     = lv0;
    ((__nv_bfloat162*)lo)[2 * j + 1] = lv1;
}

// ---------------------------------------------------------------------------
// Kernel 1: fused QKV. z=0: Q = X Wq^T (bf16 pair out); z=1: K likewise;
// z=2: V^T = Wv X^T (fp32 tf32-rounded out, pre-transposed for tf32 PV).
// ---------------------------------------------------------------------------
__global__ __launch_bounds__(NTHREADS)
void qkv_kernel()
{
    const int z = blockIdx.z;
    if (z == 0) {
        gemm_core<0>(g_xh, g_xl, DIM, g_wqh, g_wql, DIM,
                     blockIdx.y * 128, blockIdx.x * 128, DIM / BK,
                     g_qh, g_ql, nullptr, DIM);
    } else if (z == 1) {
        gemm_core<0>(g_xh, g_xl, DIM, g_wkh, g_wkl, DIM,
                     blockIdx.y * 128, blockIdx.x * 128, DIM / BK,
                     g_kh, g_kl, nullptr, DIM);
    } else {
        gemm_core<2>(g_wvh, g_wvl, DIM, g_xh, g_xl, DIM,
                     blockIdx.x * 128, blockIdx.y * 128, DIM / BK,
                     nullptr, nullptr, g_vt, NTOK);
    }
}

// ---------------------------------------------------------------------------
// Kernel 2: scores S = Q K^T (fp32), causal block skip
// ---------------------------------------------------------------------------
__global__ __launch_bounds__(NTHREADS)
void scores_kernel()
{
    const int m0 = blockIdx.y * 128, n0 = blockIdx.x * 128;
    if (n0 > m0) return;
    const int b = blockIdx.z;
    const size_t qo = (size_t)b * SEQ * DIM;
    gemm_core<1>(g_qh + qo, g_ql + qo, DIM,
                 g_kh + qo, g_kl + qo, DIM,
                 m0, n0, DIM / BK,
                 nullptr, nullptr, g_s + (size_t)b * SEQ * SEQ, SEQ);
}

// ---------------------------------------------------------------------------
// Kernel 3: causal softmax IN PLACE on g_s. Single expf pass, row in regs.
// Output tf32-rounded fp32 probs; zeros written only up to zlim = tile
// boundary (PV never reads beyond k < (q&~127)+128).
// ---------------------------------------------------------------------------
__global__ __launch_bounds__(NTHREADS)
void softmax_kernel()
{
    const int q = blockIdx.x, b = blockIdx.y;
    float* row = g_s + ((size_t)b * SEQ + q) * SEQ;
    const int nvalid = q + 1;
    const int zlim = (q & ~127) + 128;
    const int tid = threadIdx.x, lane = tid & 31, wid = tid >> 5;

    __shared__ float sred[8];

    // load 8 elements as two float4 (coalesced: tid, tid+256)
    float4 v0 = ((const float4*)row)[tid];
    float4 v1 = ((const float4*)row)[tid + 256];
    const int e0 = 4 * tid, e1 = 4 * (tid + 256);

    float f[8] = {v0.x, v0.y, v0.z, v0.w, v1.x, v1.y, v1.z, v1.w};
    int   ei[8] = {e0, e0 + 1, e0 + 2, e0 + 3, e1, e1 + 1, e1 + 2, e1 + 3};

    float mx = -INFINITY;
#pragma unroll
    for (int j = 0; j < 8; j++)
        if (ei[j] < nvalid) mx = fmaxf(mx, f[j]);
#pragma unroll
    for (int o = 16; o > 0; o >>= 1)
        mx = fmaxf(mx, __shfl_xor_sync(0xffffffffu, mx, o));
    if (lane == 0) sred[wid] = mx;
    __syncthreads();
    mx = sred[0];
#pragma unroll
    for (int w = 1; w < 8; w++) mx = fmaxf(mx, sred[w]);

    float sum = 0.0f;
#pragma unroll
    for (int j = 0; j < 8; j++) {
        f[j] = (ei[j] < nvalid) ? expf((f[j] - mx) * SCALE) : 0.0f;
        sum += f[j];
    }
#pragma unroll
    for (int o = 16; o > 0; o >>= 1)
        sum += __shfl_xor_sync(0xffffffffu, sum, o);
    __syncthreads();
    if (lane == 0) sred[wid] = sum;
    __syncthreads();
    sum = 0.0f;
#pragma unroll
    for (int w = 0; w < 8; w++) sum += sred[w];
    const float inv = 1.0f / sum;

    if (e0 < zlim) {
        float4 o0 = make_float4(to_tf32(f[0] * inv), to_tf32(f[1] * inv),
                                to_tf32(f[2] * inv), to_tf32(f[3] * inv));
        ((float4*)row)[tid] = o0;
    }
    if (e1 < zlim) {
        float4 o1 = make_float4(to_tf32(f[4] * inv), to_tf32(f[5] * inv),
                                to_tf32(f[6] * inv), to_tf32(f[7] * inv));
        ((float4*)row)[tid + 256] = o1;
    }
}

// ---------------------------------------------------------------------------
// Kernel 4: O = P V via V^T, single-term TF32 MMA, k bounded by causal diag.
// 128x128 tile, BK2=32 fp32 k-chunk (128B rows, SW128), double buffered.
// ---------------------------------------------------------------------------
__global__ __launch_bounds__(NTHREADS)
void pv_kernel(float* __restrict__ out)
{
    extern __shared__ char smem[];
    const uint32_t sbase = smem_u32(smem);
    const int tid  = threadIdx.x;
    const int lane = tid & 31;
    const int wid  = tid >> 5;
    const int wm   = wid >> 2;
    const int wn   = wid & 3;
    const int b  = blockIdx.z;
    const int m0 = blockIdx.y * 128, n0 = blockIdx.x * 128;

    const float* A0 = g_s  + (size_t)b * SEQ * SEQ + (size_t)m0 * SEQ;  // P rows
    const float* B0 = g_vt + (size_t)n0 * NTOK + (size_t)b * SEQ;       // V^T rows
    const int nIter = (m0 + 128) / BK2;

    auto load_tile = [&](int it) {
        const uint32_t db = sbase + (uint32_t)(it & 1) * PV_STAGE_B;
        const int k0 = it * BK2;
#pragma unroll
        for (int i = 0; i < 4; i++) {
            const int c = tid + i * NTHREADS;     // 0..1023
            const int row = c >> 3, ch = c & 7;
            const uint32_t so = SWZ((uint32_t)(row * 128 + ch * 16));
            cp16(db + so,             A0 + (size_t)row * SEQ  + k0 + ch * 4);
            cp16(db + PV_TILE_B + so, B0 + (size_t)row * NTOK + k0 + ch * 4);
        }
        cp_commit();
    };

    float acc[4][4][4];
#pragma unroll
    for (int i = 0; i < 4; i++)
#pragma unroll
        for (int j = 0; j < 4; j++)
#pragma unroll
            for (int v = 0; v < 4; v++) acc[i][j][v] = 0.0f;

    load_tile(0);
    load_tile(1);

    const int ar = lane >> 2;      // 0..7
    const int ac = lane & 3;       // 0..3

    for (int it = 0; it < nIter; ++it) {
        if (it + 1 < nIter) cp_wait<1>(); else cp_wait<0>();
        __syncthreads();

        const uint32_t db = sbase + (uint32_t)(it & 1) * PV_STAGE_B;
#pragma unroll
        for (int ks = 0; ks < 4; ks++) {
            const uint32_t c0 = (uint32_t)(ks * 8 + ac) * 4;   // byte col
            uint32_t a[4][4], bb[4][2];
#pragma unroll
            for (int fm = 0; fm < 4; fm++) {
                const uint32_t r = (uint32_t)(wm * 64 + fm * 16 + ar) * 128;
                a[fm][0] = lds32(db + SWZ(r + c0));
                a[fm][1] = lds32(db + SWZ(r + 1024 + c0));        // row+8
                a[fm][2] = lds32(db + SWZ(r + c0 + 16));          // col+4
                a[fm][3] = lds32(db + SWZ(r + 1024 + c0 + 16));
            }
#pragma unroll
            for (int fn = 0; fn < 4; fn++) {
                const uint32_t r = (uint32_t)(wn * 32 + fn * 8 + ar) * 128;
                bb[fn][0] = lds32(db + PV_TILE_B + SWZ(r + c0));
                bb[fn][1] = lds32(db + PV_TILE_B + SWZ(r + c0 + 16));
            }
#pragma unroll
            for (int fm = 0; fm < 4; fm++)
#pragma unroll
                for (int fn = 0; fn < 4; fn++)
                    mma1688t(acc[fm][fn], a[fm], bb[fn]);
        }
        __syncthreads();
        if (it + 2 < nIter) load_tile(it + 2);
    }

    float* O = out + (size_t)b * SEQ * DIM;
    const int er = lane >> 2;
    const int ec = (lane & 3) * 2;
#pragma unroll
    for (int fm = 0; fm < 4; fm++) {
#pragma unroll
        for (int fn = 0; fn < 4; fn++) {
            const int r0 = m0 + wm * 64 + fm * 16 + er;
            const int r1 = r0 + 8;
            const int c  = n0 + wn * 32 + fn * 8 + ec;
            *(float2*)(O + (size_t)r0 * DIM + c) = make_float2(acc[fm][fn][0], acc[fm][fn][1]);
            *(float2*)(O + (size_t)r1 * DIM + c) = make_float2(acc[fm][fn][2], acc[fm][fn][3]);
        }
    }
}

// ---------------------------------------------------------------------------
extern "C" void kernel_launch(void* const* d_in, const int* in_sizes, int n_in,
                              void* d_out, int out_size)
{
    const float* x  = (const float*)d_in[0];
    const float* wq = (const float*)d_in[1];
    const float* wk = (const float*)d_in[2];
    const float* wv = (const float*)d_in[3];
    float* out = (float*)d_out;

    cudaFuncSetAttribute(qkv_kernel,    cudaFuncAttributeMaxDynamicSharedMemorySize, SMEM_BYTES);
    cudaFuncSetAttribute(scores_kernel, cudaFuncAttributeMaxDynamicSharedMemorySize, SMEM_BYTES);
    cudaFuncSetAttribute(pv_kernel,     cudaFuncAttributeMaxDynamicSharedMemorySize, PV_SMEM);

    const int ntot = NX4 + 3 * NW4;
    convert_all_kernel<<<(ntot + NTHREADS - 1) / NTHREADS, NTHREADS>>>(x, wq, wk, wv);

    qkv_kernel<<<dim3(DIM / 128, NTOK / 128, 3), NTHREADS, SMEM_BYTES>>>();
    scores_kernel<<<dim3(SEQ / 128, SEQ / 128, BATCH), NTHREADS, SMEM_BYTES>>>();
    softmax_kernel<<<dim3(SEQ, BATCH), NTHREADS>>>();
    pv_kernel<<<dim3(DIM / 128, SEQ / 128, BATCH), NTHREADS, PV_SMEM>>>(out);
}

// round 6
// speedup vs baseline: 3.7197x; 1.1126x over previous
#include <cuda_runtime.h>
#include <cuda_bf16.h>
#include <math.h>
#include <stdint.h>

// ---------------------------------------------------------------------------
// Problem constants
// ---------------------------------------------------------------------------
#define BATCH 4
#define SEQ   2048
#define DIM   768
#define NTOK  (BATCH * SEQ)          // 8192
#define NTHREADS 256
#define SCALE 0.03608439182435161f   // 1/sqrt(768)

// bf16 GEMM tiling: 128x128 CTA tile, K chunk of 64 bf16 (128B rows, SW128)
#define BK 64
#define TILE_B  16384
#define STAGE_B (4 * TILE_B)
#define SMEM_BYTES (2 * STAGE_B)     // 128 KB

// tf32 tiling: 128x128 CTA tile, K chunk of 32 fp32 (128B rows, SW128)
#define BK2 32
#define PV_TILE_B  16384
#define PV_STAGE_B (2 * PV_TILE_B)
#define PV_SMEM    (2 * PV_STAGE_B)  // 64 KB

#define SWZ(o) ((o) ^ ((((uint32_t)(o)) >> 3) & 0x70))

// ---------------------------------------------------------------------------
// Scratch (__device__ globals; referenced ONLY from device code)
// ---------------------------------------------------------------------------
__device__ __align__(128) __nv_bfloat16 g_xh[NTOK * DIM], g_xl[NTOK * DIM];
__device__ __align__(128) float         g_xt[NTOK * DIM];        // tf32-rounded x
__device__ __align__(128) __nv_bfloat16 g_wqTh[DIM * DIM], g_wqTl[DIM * DIM]; // Wq^T pair
__device__ __align__(128) __nv_bfloat16 g_wkTh[DIM * DIM], g_wkTl[DIM * DIM]; // Wk^T pair
__device__ __align__(128) float         g_wvt[DIM * DIM];        // tf32-rounded wv
__device__ __align__(128) __nv_bfloat16 g_mh[DIM * DIM], g_ml[DIM * DIM];     // Mrow pair
__device__ __align__(128) __nv_bfloat16 g_yh[NTOK * DIM], g_yl[NTOK * DIM];   // Y = X*Mrow^T
__device__ __align__(128) float         g_vt[DIM * NTOK];        // V^T tf32-rounded
__device__ __align__(128) float         g_s[(size_t)BATCH * SEQ * SEQ];       // S -> P

// ---------------------------------------------------------------------------
// PTX helpers (plain compute_80-class)
// ---------------------------------------------------------------------------
__device__ __forceinline__ uint32_t smem_u32(const void* p) {
    uint32_t a;
    asm("{ .reg .u64 t; cvta.to.shared.u64 t, %1; cvt.u32.u64 %0, t; }"
        : "=r"(a) : "l"(p));
    return a;
}
__device__ __forceinline__ void cp16(uint32_t dst, const void* src) {
    asm volatile("cp.async.cg.shared.global [%0], [%1], 16;" :: "r"(dst), "l"(src));
}
__device__ __forceinline__ void cp_commit() {
    asm volatile("cp.async.commit_group;" ::: "memory");
}
template <int N>
__device__ __forceinline__ void cp_wait() {
    asm volatile("cp.async.wait_group %0;" :: "n"(N) : "memory");
}
__device__ __forceinline__ void ldsm4(uint32_t addr, uint32_t* r) {
    asm volatile("ldmatrix.sync.aligned.m8n8.x4.shared.b16 {%0,%1,%2,%3}, [%4];"
                 : "=r"(r[0]), "=r"(r[1]), "=r"(r[2]), "=r"(r[3]) : "r"(addr));
}
__device__ __forceinline__ void ldsm2(uint32_t addr, uint32_t* r) {
    asm volatile("ldmatrix.sync.aligned.m8n8.x2.shared.b16 {%0,%1}, [%2];"
                 : "=r"(r[0]), "=r"(r[1]) : "r"(addr));
}
__device__ __forceinline__ void mma16816(float* d, const uint32_t* a, const uint32_t* b) {
    asm volatile(
        "mma.sync.aligned.m16n8k16.row.col.f32.bf16.bf16.f32 "
        "{%0,%1,%2,%3}, {%4,%5,%6,%7}, {%8,%9}, {%0,%1,%2,%3};"
        : "+f"(d[0]), "+f"(d[1]), "+f"(d[2]), "+f"(d[3])
        : "r"(a[0]), "r"(a[1]), "r"(a[2]), "r"(a[3]), "r"(b[0]), "r"(b[1]));
}
__device__ __forceinline__ void mma1688t(float* d, const uint32_t* a, const uint32_t* b) {
    asm volatile(
        "mma.sync.aligned.m16n8k8.row.col.f32.tf32.tf32.f32 "
        "{%0,%1,%2,%3}, {%4,%5,%6,%7}, {%8,%9}, {%0,%1,%2,%3};"
        : "+f"(d[0]), "+f"(d[1]), "+f"(d[2]), "+f"(d[3])
        : "r"(a[0]), "r"(a[1]), "r"(a[2]), "r"(a[3]), "r"(b[0]), "r"(b[1]));
}
__device__ __forceinline__ uint32_t lds32(uint32_t addr) {
    uint32_t v;
    asm volatile("ld.shared.b32 %0, [%1];" : "=r"(v) : "r"(addr));
    return v;
}
__device__ __forceinline__ float to_tf32(float x) {
    float r;
    asm("cvt.rna.tf32.f32 %0, %1;" : "=f"(r) : "f"(x));
    return r;
}

// ---------------------------------------------------------------------------
// 128x128 NT GEMM tile, split-bf16 3-term: D ~= (Ah+Al)(Bh+Bl)^T
// EPI 0: bf16 hi/lo pair out.  EPI 1: fp32 out.
// ---------------------------------------------------------------------------
template <int EPI>
__device__ __forceinline__ void gemm_core(
    const __nv_bfloat16* __restrict__ Ah, const __nv_bfloat16* __restrict__ Al, int lda,
    const __nv_bfloat16* __restrict__ Bh, const __nv_bfloat16* __restrict__ Bl, int ldb,
    int m0, int n0, int nIter,
    __nv_bfloat16* __restrict__ Oh, __nv_bfloat16* __restrict__ Ol,
    float* __restrict__ Of, int ldc)
{
    extern __shared__ char smem[];
    const uint32_t sbase = smem_u32(smem);
    const int tid  = threadIdx.x;
    const int lane = tid & 31;
    const int wid  = tid >> 5;
    const int wm   = wid >> 2;
    const int wn   = wid & 3;

    const __nv_bfloat16* A0h = Ah + (size_t)m0 * lda;
    const __nv_bfloat16* A0l = Al + (size_t)m0 * lda;
    const __nv_bfloat16* B0h = Bh + (size_t)n0 * ldb;
    const __nv_bfloat16* B0l = Bl + (size_t)n0 * ldb;

    auto load_tile = [&](int it) {
        const uint32_t db = sbase + (uint32_t)(it & 1) * STAGE_B;
        const int k0 = it * BK;
#pragma unroll
        for (int i = 0; i < 4; i++) {
            const int c = tid + i * NTHREADS;
            const int row = c >> 3, ch = c & 7;
            const uint32_t so = SWZ((uint32_t)(row * 128 + ch * 16));
            const size_t ga = (size_t)row * lda + k0 + ch * 8;
            const size_t gb = (size_t)row * ldb + k0 + ch * 8;
            cp16(db + so,              A0h + ga);
            cp16(db + TILE_B + so,     A0l + ga);
            cp16(db + 2 * TILE_B + so, B0h + gb);
            cp16(db + 3 * TILE_B + so, B0l + gb);
        }
        cp_commit();
    };

    float acc[4][4][4];
#pragma unroll
    for (int i = 0; i < 4; i++)
#pragma unroll
        for (int j = 0; j < 4; j++)
#pragma unroll
            for (int v = 0; v < 4; v++) acc[i][j][v] = 0.0f;

    const uint32_t a_l = ((uint32_t)(lane & 15) << 7) + ((uint32_t)(lane >> 4) << 4);
    const uint32_t b_l = ((uint32_t)(lane & 7) << 7) + ((uint32_t)((lane >> 3) & 1) << 4);

    load_tile(0);
    load_tile(1);

    for (int it = 0; it < nIter; ++it) {
        if (it + 1 < nIter) cp_wait<1>(); else cp_wait<0>();
        __syncthreads();

        const uint32_t db = sbase + (uint32_t)(it & 1) * STAGE_B;
#pragma unroll
        for (int ks = 0; ks < 4; ks++) {
            uint32_t ah[4][4], al_[4][4], bh[4][2], bl_[4][2];
#pragma unroll
            for (int fm = 0; fm < 4; fm++) {
                const uint32_t sw = SWZ(((uint32_t)(wm * 64 + fm * 16) << 7) +
                                        (uint32_t)(ks * 32) + a_l);
                ldsm4(db + sw, ah[fm]);
                ldsm4(db + TILE_B + sw, al_[fm]);
            }
#pragma unroll
            for (int fn = 0; fn < 4; fn++) {
                const uint32_t sw = SWZ(((uint32_t)(wn * 32 + fn * 8) << 7) +
                                        (uint32_t)(ks * 32) + b_l);
                ldsm2(db + 2 * TILE_B + sw, bh[fn]);
                ldsm2(db + 3 * TILE_B + sw, bl_[fn]);
            }
#pragma unroll
            for (int fm = 0; fm < 4; fm++)
#pragma unroll
                for (int fn = 0; fn < 4; fn++)
                    mma16816(acc[fm][fn], ah[fm], bh[fn]);
#pragma unroll
            for (int fm = 0; fm < 4; fm++)
#pragma unroll
                for (int fn = 0; fn < 4; fn++)
                    mma16816(acc[fm][fn], ah[fm], bl_[fn]);
#pragma unroll
            for (int fm = 0; fm < 4; fm++)
#pragma unroll
                for (int fn = 0; fn < 4; fn++)
                    mma16816(acc[fm][fn], al_[fm], bh[fn]);
        }
        __syncthreads();
        if (it + 2 < nIter) load_tile(it + 2);
    }

    const int er = lane >> 2;
    const int ec = (lane & 3) * 2;
#pragma unroll
    for (int fm = 0; fm < 4; fm++) {
#pragma unroll
        for (int fn = 0; fn < 4; fn++) {
            const int r0 = m0 + wm * 64 + fm * 16 + er;
            const int r1 = r0 + 8;
            const int c  = n0 + wn * 32 + fn * 8 + ec;
            if (EPI == 1) {
                *(float2*)(Of + (size_t)r0 * ldc + c) = make_float2(acc[fm][fn][0], acc[fm][fn][1]);
                *(float2*)(Of + (size_t)r1 * ldc + c) = make_float2(acc[fm][fn][2], acc[fm][fn][3]);
            } else {
#pragma unroll
                for (int p = 0; p < 2; p++) {
                    const int rr = p == 0 ? r0 : r1;
                    const float f0 = acc[fm][fn][2 * p];
                    const float f1 = acc[fm][fn][2 * p + 1];
                    const __nv_bfloat16 h0 = __float2bfloat16(f0);
                    const __nv_bfloat16 h1 = __float2bfloat16(f1);
                    __nv_bfloat162 hv; hv.x = h0; hv.y = h1;
                    __nv_bfloat162 lv;
                    lv.x = __float2bfloat16(f0 - __bfloat162float(h0));
                    lv.y = __float2bfloat16(f1 - __bfloat162float(h1));
                    *(__nv_bfloat162*)(Oh + (size_t)rr * ldc + c) = hv;
                    *(__nv_bfloat162*)(Ol + (size_t)rr * ldc + c) = lv;
                }
            }
        }
    }
}

// ---------------------------------------------------------------------------
// 128x128 NT GEMM tile, single-term TF32 (operands pre-rounded to tf32).
// ROUND 1: round output to tf32.  ROUND 0: plain fp32 out.
// ---------------------------------------------------------------------------
template <int ROUND>
__device__ __forceinline__ void tf32_core(
    const float* __restrict__ A, int lda,
    const float* __restrict__ B, int ldb,
    int m0, int n0, int nIter,
    float* __restrict__ C, int ldc)
{
    extern __shared__ char smem[];
    const uint32_t sbase = smem_u32(smem);
    const int tid  = threadIdx.x;
    const int lane = tid & 31;
    const int wid  = tid >> 5;
    const int wm   = wid >> 2;
    const int wn   = wid & 3;

    const float* A0 = A + (size_t)m0 * lda;
    const float* B0 = B + (size_t)n0 * ldb;

    auto load_tile = [&](int it) {
        const uint32_t db = sbase + (uint32_t)(it & 1) * PV_STAGE_B;
        const int k0 = it * BK2;
#pragma unroll
        for (int i = 0; i < 4; i++) {
            const int c = tid + i * NTHREADS;
            const int row = c >> 3, ch = c & 7;
            const uint32_t so = SWZ((uint32_t)(row * 128 + ch * 16));
            cp16(db + so,             A0 + (size_t)row * lda + k0 + ch * 4);
            cp16(db + PV_TILE_B + so, B0 + (size_t)row * ldb + k0 + ch * 4);
        }
        cp_commit();
    };

    float acc[4][4][4];
#pragma unroll
    for (int i = 0; i < 4; i++)
#pragma unroll
        for (int j = 0; j < 4; j++)
#pragma unroll
            for (int v = 0; v < 4; v++) acc[i][j][v] = 0.0f;

    load_tile(0);
    load_tile(1);

    const int ar = lane >> 2;
    const int ac = lane & 3;

    for (int it = 0; it < nIter; ++it) {
        if (it + 1 < nIter) cp_wait<1>(); else cp_wait<0>();
        __syncthreads();

        const uint32_t db = sbase + (uint32_t)(it & 1) * PV_STAGE_B;
#pragma unroll
        for (int ks = 0; ks < 4; ks++) {
            const uint32_t c0 = (uint32_t)(ks * 8 + ac) * 4;
            uint32_t a[4][4], bb[4][2];
#pragma unroll
            for (int fm = 0; fm < 4; fm++) {
                const uint32_t r = (uint32_t)(wm * 64 + fm * 16 + ar) * 128;
                a[fm][0] = lds32(db + SWZ(r + c0));
                a[fm][1] = lds32(db + SWZ(r + 1024 + c0));
                a[fm][2] = lds32(db + SWZ(r + c0 + 16));
                a[fm][3] = lds32(db + SWZ(r + 1024 + c0 + 16));
            }
#pragma unroll
            for (int fn = 0; fn < 4; fn++) {
                const uint32_t r = (uint32_t)(wn * 32 + fn * 8 + ar) * 128;
                bb[fn][0] = lds32(db + PV_TILE_B + SWZ(r + c0));
                bb[fn][1] = lds32(db + PV_TILE_B + SWZ(r + c0 + 16));
            }
#pragma unroll
            for (int fm = 0; fm < 4; fm++)
#pragma unroll
                for (int fn = 0; fn < 4; fn++)
                    mma1688t(acc[fm][fn], a[fm], bb[fn]);
        }
        __syncthreads();
        if (it + 2 < nIter) load_tile(it + 2);
    }

    const int er = lane >> 2;
    const int ec = (lane & 3) * 2;
#pragma unroll
    for (int fm = 0; fm < 4; fm++) {
#pragma unroll
        for (int fn = 0; fn < 4; fn++) {
            const int r0 = m0 + wm * 64 + fm * 16 + er;
            const int r1 = r0 + 8;
            const int c  = n0 + wn * 32 + fn * 8 + ec;
            if (ROUND) {
                *(float2*)(C + (size_t)r0 * ldc + c) =
                    make_float2(to_tf32(acc[fm][fn][0]), to_tf32(acc[fm][fn][1]));
                *(float2*)(C + (size_t)r1 * ldc + c) =
                    make_float2(to_tf32(acc[fm][fn][2]), to_tf32(acc[fm][fn][3]));
            } else {
                *(float2*)(C + (size_t)r0 * ldc + c) = make_float2(acc[fm][fn][0], acc[fm][fn][1]);
                *(float2*)(C + (size_t)r1 * ldc + c) = make_float2(acc[fm][fn][2], acc[fm][fn][3]);
            }
        }
    }
}

// ---------------------------------------------------------------------------
// Kernel 0: convert. x -> (xh, xl, xt); wv -> wvt (tf32-rounded fp32).
// ---------------------------------------------------------------------------
#define NX4 (NTOK * DIM / 4)
#define NW4 (DIM * DIM / 4)

__global__ __launch_bounds__(NTHREADS)
void convert_kernel(const float* __restrict__ x, const float* __restrict__ wv)
{
    const int i = blockIdx.x * NTHREADS + threadIdx.x;
    if (i < NX4) {
        const float4 v = ((const float4*)x)[i];
        const __nv_bfloat16 h0 = __float2bfloat16(v.x), h1 = __float2bfloat16(v.y);
        const __nv_bfloat16 h2 = __float2bfloat16(v.z), h3 = __float2bfloat16(v.w);
        __nv_bfloat162 hv0, hv1, lv0, lv1;
        hv0.x = h0; hv0.y = h1; hv1.x = h2; hv1.y = h3;
        lv0.x = __float2bfloat16(v.x - __bfloat162float(h0));
        lv0.y = __float2bfloat16(v.y - __bfloat162float(h1));
        lv1.x = __float2bfloat16(v.z - __bfloat162float(h2));
        lv1.y = __float2bfloat16(v.w - __bfloat162float(h3));
        ((__nv_bfloat162*)g_xh)[2 * i]     = hv0;
        ((__nv_bfloat162*)g_xh)[2 * i + 1] = hv1;
        ((__nv_bfloat162*)g_xl)[2 * i]     = lv0;
        ((__nv_bfloat162*)g_xl)[2 * i + 1] = lv1;
        ((float4*)g_xt)[i] = make_float4(to_tf32(v.x), to_tf32(v.y),
                                         to_tf32(v.z), to_tf32(v.w));
    } else if (i < NX4 + NW4) {
        const int j = i - NX4;
        const float4 v = ((const float4*)wv)[j];
        ((float4*)g_wvt)[j] = make_float4(to_tf32(v.x), to_tf32(v.y),
                                          to_tf32(v.z), to_tf32(v.w));
    }
}

// ---------------------------------------------------------------------------
// Kernel 1: tiled transpose wq, wk -> bf16 hi/lo pairs of W^T.
// grid (24, 24, 2), block 256 (32x8).
// ---------------------------------------------------------------------------
__global__ __launch_bounds__(NTHREADS)
void transpose_w_kernel(const float* __restrict__ wq, const float* __restrict__ wk)
{
    __shared__ float t[32][33];
    const float* src = blockIdx.z ? wk : wq;
    __nv_bfloat16* oh = blockIdx.z ? g_wkTh : g_wqTh;
    __nv_bfloat16* ol = blockIdx.z ? g_wkTl : g_wqTl;
    const int tx = threadIdx.x & 31, ty = threadIdx.x >> 5;
    const int c0 = blockIdx.x * 32, r0 = blockIdx.y * 32;
#pragma unroll
    for (int i = 0; i < 4; i++)
        t[ty + i * 8][tx] = src[(size_t)(r0 + ty + i * 8) * DIM + c0 + tx];
    __syncthreads();
#pragma unroll
    for (int i = 0; i < 4; i++) {
        const int d = c0 + ty + i * 8;  // output row (original col)
        const int e = r0 + tx;          // output col (original row)
        const float v = t[tx][ty + i * 8];
        const __nv_bfloat16 h = __float2bfloat16(v);
        oh[(size_t)d * DIM + e] = h;
        ol[(size_t)d * DIM + e] = __float2bfloat16(v - __bfloat162float(h));
    }
}

// ---------------------------------------------------------------------------
// Kernel 2: fused V + M.
//   CTA < 384:  V^T = Wv X^T, single-term tf32, out g_vt (tf32-rounded)
//   CTA >= 384: Mrow = Wk^T(pair) x Wq^T(pair) NT 3-term, out g_mh/g_ml
//               Mrow[d2][k] = sum_e wk[e][d2] * wq[e][k]
// ---------------------------------------------------------------------------
__global__ __launch_bounds__(NTHREADS)
void vm_kernel()
{
    const int cta = blockIdx.x;
    if (cta < 384) {
        const int mi = cta / 64, ni = cta % 64;
        tf32_core<1>(g_wvt, DIM, g_xt, DIM,
                     mi * 128, ni * 128, DIM / BK2, g_vt, NTOK);
    } else {
        const int c2 = cta - 384;
        const int mi = c2 / 6, ni = c2 % 6;
        gemm_core<0>(g_wkTh, g_wkTl, DIM, g_wqTh, g_wqTl, DIM,
                     mi * 128, ni * 128, DIM / BK,
                     g_mh, g_ml, nullptr, DIM);
    }
}

// ---------------------------------------------------------------------------
// Kernel 3: Y = X * Mrow^T (NT, 3-term), out bf16 pair. grid (6, 64).
// ---------------------------------------------------------------------------
__global__ __launch_bounds__(NTHREADS)
void y_kernel()
{
    gemm_core<0>(g_xh, g_xl, DIM, g_mh, g_ml, DIM,
                 blockIdx.y * 128, blockIdx.x * 128, DIM / BK,
                 g_yh, g_yl, nullptr, DIM);
}

// ---------------------------------------------------------------------------
// Kernel 4: scores S = Y X^T (== Q K^T), causal block skip. grid (16,16,4).
// ---------------------------------------------------------------------------
__global__ __launch_bounds__(NTHREADS)
void scores_kernel()
{
    const int m0 = blockIdx.y * 128, n0 = blockIdx.x * 128;
    if (n0 > m0) return;
    const int b = blockIdx.z;
    const size_t o = (size_t)b * SEQ * DIM;
    gemm_core<1>(g_yh + o, g_yl + o, DIM,
                 g_xh + o, g_xl + o, DIM,
                 m0, n0, DIM / BK,
                 nullptr, nullptr, g_s + (size_t)b * SEQ * SEQ, SEQ);
}

// ---------------------------------------------------------------------------
// Kernel 5: causal softmax in place, tf32-rounded probs, reads/writes
// bounded by nvalid / zlim.
// ---------------------------------------------------------------------------
__global__ __launch_bounds__(NTHREADS)
void softmax_kernel()
{
    const int q = blockIdx.x, b = blockIdx.y;
    float* row = g_s + ((size_t)b * SEQ + q) * SEQ;
    const int nvalid = q + 1;
    const int zlim = (q & ~127) + 128;
    const int tid = threadIdx.x, lane = tid & 31, wid = tid >> 5;

    __shared__ float sred[8];

    const int e0 = 4 * tid, e1 = 4 * (tid + 256);
    float4 v0 = (e0 < nvalid) ? ((const float4*)row)[tid]
                              : make_float4(0.f, 0.f, 0.f, 0.f);
    float4 v1 = (e1 < nvalid) ? ((const float4*)row)[tid + 256]
                              : make_float4(0.f, 0.f, 0.f, 0.f);

    float f[8] = {v0.x, v0.y, v0.z, v0.w, v1.x, v1.y, v1.z, v1.w};
    int   ei[8] = {e0, e0 + 1, e0 + 2, e0 + 3, e1, e1 + 1, e1 + 2, e1 + 3};

    float mx = -INFINITY;
#pragma unroll
    for (int j = 0; j < 8; j++)
        if (ei[j] < nvalid) mx = fmaxf(mx, f[j]);
#pragma unroll
    for (int o = 16; o > 0; o >>= 1)
        mx = fmaxf(mx, __shfl_xor_sync(0xffffffffu, mx, o));
    if (lane == 0) sred[wid] = mx;
    __syncthreads();
    mx = sred[0];
#pragma unroll
    for (int w = 1; w < 8; w++) mx = fmaxf(mx, sred[w]);

    float sum = 0.0f;
#pragma unroll
    for (int j = 0; j < 8; j++) {
        f[j] = (ei[j] < nvalid) ? expf((f[j] - mx) * SCALE) : 0.0f;
        sum += f[j];
    }
#pragma unroll
    for (int o = 16; o > 0; o >>= 1)
        sum += __shfl_xor_sync(0xffffffffu, sum, o);
    __syncthreads();
    if (lane == 0) sred[wid] = sum;
    __syncthreads();
    sum = 0.0f;
#pragma unroll
    for (int w = 0; w < 8; w++) sum += sred[w];
    const float inv = 1.0f / sum;

    if (e0 < zlim)
        ((float4*)row)[tid] = make_float4(to_tf32(f[0] * inv), to_tf32(f[1] * inv),
                                          to_tf32(f[2] * inv), to_tf32(f[3] * inv));
    if (e1 < zlim)
        ((float4*)row)[tid + 256] = make_float4(to_tf32(f[4] * inv), to_tf32(f[5] * inv),
                                                to_tf32(f[6] * inv), to_tf32(f[7] * inv));
}

// ---------------------------------------------------------------------------
// Kernel 6: O = P V via V^T, single-term tf32, k bounded by causal diagonal.
// ---------------------------------------------------------------------------
__global__ __launch_bounds__(NTHREADS)
void pv_kernel(float* __restrict__ out)
{
    const int b = blockIdx.z;
    const int m0 = blockIdx.y * 128, n0 = blockIdx.x * 128;
    tf32_core<0>(g_s + (size_t)b * SEQ * SEQ, SEQ,
                 g_vt + (size_t)b * SEQ, NTOK,
                 m0, n0, (m0 + 128) / BK2,
                 out + (size_t)b * SEQ * DIM, DIM);
}

// ---------------------------------------------------------------------------
extern "C" void kernel_launch(void* const* d_in, const int* in_sizes, int n_in,
                              void* d_out, int out_size)
{
    const float* x  = (const float*)d_in[0];
    const float* wq = (const float*)d_in[1];
    const float* wk = (const float*)d_in[2];
    const float* wv = (const float*)d_in[3];
    float* out = (float*)d_out;

    cudaFuncSetAttribute(vm_kernel,     cudaFuncAttributeMaxDynamicSharedMemorySize, SMEM_BYTES);
    cudaFuncSetAttribute(y_kernel,      cudaFuncAttributeMaxDynamicSharedMemorySize, SMEM_BYTES);
    cudaFuncSetAttribute(scores_kernel, cudaFuncAttributeMaxDynamicSharedMemorySize, SMEM_BYTES);
    cudaFuncSetAttribute(pv_kernel,     cudaFuncAttributeMaxDynamicSharedMemorySize, PV_SMEM);

    const int ntot = NX4 + NW4;
    convert_kernel<<<(ntot + NTHREADS - 1) / NTHREADS, NTHREADS>>>(x, wv);
    transpose_w_kernel<<<dim3(24, 24, 2), NTHREADS>>>(wq, wk);
    vm_kernel<<<420, NTHREADS, SMEM_BYTES>>>();
    y_kernel<<<dim3(DIM / 128, NTOK / 128), NTHREADS, SMEM_BYTES>>>();
    scores_kernel<<<dim3(SEQ / 128, SEQ / 128, BATCH), NTHREADS, SMEM_BYTES>>>();
    softmax_kernel<<<dim3(SEQ, BATCH), NTHREADS>>>();
    pv_kernel<<<dim3(DIM / 128, SEQ / 128, BATCH), NTHREADS, PV_SMEM>>>(out);
}

// round 7
// speedup vs baseline: 3.7726x; 1.0142x over previous
#include <cuda_runtime.h>
#include <cuda_bf16.h>
#include <math.h>
#include <stdint.h>

// ---------------------------------------------------------------------------
// Problem constants
// ---------------------------------------------------------------------------
#define BATCH 4
#define SEQ   2048
#define DIM   768
#define NTOK  (BATCH * SEQ)          // 8192
#define NTHREADS 256
#define SCALE 0.03608439182435161f   // 1/sqrt(768)

// bf16 GEMM tiling: 128x128 CTA tile, K chunk of 32 bf16 (64B rows, SW64)
#define BK 32
#define TILE_B  8192                 // 128 rows * 64 B
#define STAGE_B (4 * TILE_B)         // 32 KB
#define SMEM_BYTES (2 * STAGE_B)     // 64 KB -> 2 CTAs/SM

// tf32 tiling: 128x128 CTA tile, K chunk of 32 fp32 (128B rows, SW128)
#define BK2 32
#define PV_TILE_B  16384
#define PV_STAGE_B (2 * PV_TILE_B)
#define PV_SMEM    (2 * PV_STAGE_B)  // 64 KB

#define SWZ(o)   ((o) ^ ((((uint32_t)(o)) >> 3) & 0x70))   // SW128 (128B rows)
#define SWZ64(o) ((o) ^ ((((uint32_t)(o)) >> 3) & 0x30))   // SW64  (64B rows)

// ---------------------------------------------------------------------------
// Scratch (__device__ globals; referenced ONLY from device code)
// ---------------------------------------------------------------------------
__device__ __align__(128) __nv_bfloat16 g_xh[NTOK * DIM], g_xl[NTOK * DIM];
__device__ __align__(128) float         g_xt[NTOK * DIM];
__device__ __align__(128) __nv_bfloat16 g_wqTh[DIM * DIM], g_wqTl[DIM * DIM];
__device__ __align__(128) __nv_bfloat16 g_wkTh[DIM * DIM], g_wkTl[DIM * DIM];
__device__ __align__(128) float         g_wvt[DIM * DIM];
__device__ __align__(128) __nv_bfloat16 g_mh[DIM * DIM], g_ml[DIM * DIM];
__device__ __align__(128) __nv_bfloat16 g_yh[NTOK * DIM], g_yl[NTOK * DIM];
__device__ __align__(128) float         g_vt[DIM * NTOK];
__device__ __align__(128) float         g_s[(size_t)BATCH * SEQ * SEQ];

// ---------------------------------------------------------------------------
// PTX helpers
// ---------------------------------------------------------------------------
__device__ __forceinline__ uint32_t smem_u32(const void* p) {
    uint32_t a;
    asm("{ .reg .u64 t; cvta.to.shared.u64 t, %1; cvt.u32.u64 %0, t; }"
        : "=r"(a) : "l"(p));
    return a;
}
__device__ __forceinline__ void cp16(uint32_t dst, const void* src) {
    asm volatile("cp.async.cg.shared.global [%0], [%1], 16;" :: "r"(dst), "l"(src));
}
__device__ __forceinline__ void cp_commit() {
    asm volatile("cp.async.commit_group;" ::: "memory");
}
template <int N>
__device__ __forceinline__ void cp_wait() {
    asm volatile("cp.async.wait_group %0;" :: "n"(N) : "memory");
}
__device__ __forceinline__ void ldsm4(uint32_t addr, uint32_t* r) {
    asm volatile("ldmatrix.sync.aligned.m8n8.x4.shared.b16 {%0,%1,%2,%3}, [%4];"
                 : "=r"(r[0]), "=r"(r[1]), "=r"(r[2]), "=r"(r[3]) : "r"(addr));
}
__device__ __forceinline__ void ldsm2(uint32_t addr, uint32_t* r) {
    asm volatile("ldmatrix.sync.aligned.m8n8.x2.shared.b16 {%0,%1}, [%2];"
                 : "=r"(r[0]), "=r"(r[1]) : "r"(addr));
}
__device__ __forceinline__ void mma16816(float* d, const uint32_t* a, const uint32_t* b) {
    asm volatile(
        "mma.sync.aligned.m16n8k16.row.col.f32.bf16.bf16.f32 "
        "{%0,%1,%2,%3}, {%4,%5,%6,%7}, {%8,%9}, {%0,%1,%2,%3};"
        : "+f"(d[0]), "+f"(d[1]), "+f"(d[2]), "+f"(d[3])
        : "r"(a[0]), "r"(a[1]), "r"(a[2]), "r"(a[3]), "r"(b[0]), "r"(b[1]));
}
__device__ __forceinline__ void mma1688t(float* d, const uint32_t* a, const uint32_t* b) {
    asm volatile(
        "mma.sync.aligned.m16n8k8.row.col.f32.tf32.tf32.f32 "
        "{%0,%1,%2,%3}, {%4,%5,%6,%7}, {%8,%9}, {%0,%1,%2,%3};"
        : "+f"(d[0]), "+f"(d[1]), "+f"(d[2]), "+f"(d[3])
        : "r"(a[0]), "r"(a[1]), "r"(a[2]), "r"(a[3]), "r"(b[0]), "r"(b[1]));
}
__device__ __forceinline__ uint32_t lds32(uint32_t addr) {
    uint32_t v;
    asm volatile("ld.shared.b32 %0, [%1];" : "=r"(v) : "r"(addr));
    return v;
}
__device__ __forceinline__ float to_tf32(float x) {
    float r;
    asm("cvt.rna.tf32.f32 %0, %1;" : "=f"(r) : "f"(x));
    return r;
}

// ---------------------------------------------------------------------------
// 128x128 NT GEMM tile, split-bf16 3-term, BK=32, SW64, 64KB smem.
// EPI 0: bf16 hi/lo pair out.  EPI 1: fp32 out.
// ---------------------------------------------------------------------------
template <int EPI>
__device__ __forceinline__ void gemm_core(
    const __nv_bfloat16* __restrict__ Ah, const __nv_bfloat16* __restrict__ Al, int lda,
    const __nv_bfloat16* __restrict__ Bh, const __nv_bfloat16* __restrict__ Bl, int ldb,
    int m0, int n0, int nIter,
    __nv_bfloat16* __restrict__ Oh, __nv_bfloat16* __restrict__ Ol,
    float* __restrict__ Of, int ldc)
{
    extern __shared__ char smem[];
    const uint32_t sbase = smem_u32(smem);
    const int tid  = threadIdx.x;
    const int lane = tid & 31;
    const int wid  = tid >> 5;
    const int wm   = wid >> 2;
    const int wn   = wid & 3;

    const __nv_bfloat16* A0h = Ah + (size_t)m0 * lda;
    const __nv_bfloat16* A0l = Al + (size_t)m0 * lda;
    const __nv_bfloat16* B0h = Bh + (size_t)n0 * ldb;
    const __nv_bfloat16* B0l = Bl + (size_t)n0 * ldb;

    // 512 16B-chunks per 8KB tile; 2 chunks/thread/tile
    auto load_tile = [&](int it) {
        const uint32_t db = sbase + (uint32_t)(it & 1) * STAGE_B;
        const int k0 = it * BK;
#pragma unroll
        for (int i = 0; i < 2; i++) {
            const int c = tid + i * NTHREADS;        // 0..511
            const int row = c >> 2, ch = c & 3;
            const uint32_t so = SWZ64((uint32_t)(row * 64 + ch * 16));
            const size_t ga = (size_t)row * lda + k0 + ch * 8;
            const size_t gb = (size_t)row * ldb + k0 + ch * 8;
            cp16(db + so,              A0h + ga);
            cp16(db + TILE_B + so,     A0l + ga);
            cp16(db + 2 * TILE_B + so, B0h + gb);
            cp16(db + 3 * TILE_B + so, B0l + gb);
        }
        cp_commit();
    };

    float acc[4][4][4];
#pragma unroll
    for (int i = 0; i < 4; i++)
#pragma unroll
        for (int j = 0; j < 4; j++)
#pragma unroll
            for (int v = 0; v < 4; v++) acc[i][j][v] = 0.0f;

    // per-lane ldmatrix address components (64B rows)
    const uint32_t a_l = ((uint32_t)(lane & 15) << 6) + ((uint32_t)(lane >> 4) << 4);
    const uint32_t b_l = ((uint32_t)(lane & 7) << 6) + ((uint32_t)((lane >> 3) & 1) << 4);

    load_tile(0);
    load_tile(1);

    for (int it = 0; it < nIter; ++it) {
        if (it + 1 < nIter) cp_wait<1>(); else cp_wait<0>();
        __syncthreads();

        const uint32_t db = sbase + (uint32_t)(it & 1) * STAGE_B;
#pragma unroll
        for (int ks = 0; ks < 2; ks++) {
            uint32_t ah[4][4], al_[4][4], bh[4][2], bl_[4][2];
#pragma unroll
            for (int fm = 0; fm < 4; fm++) {
                const uint32_t sw = SWZ64(((uint32_t)(wm * 64 + fm * 16) << 6) +
                                          (uint32_t)(ks * 32) + a_l);
                ldsm4(db + sw, ah[fm]);
                ldsm4(db + TILE_B + sw, al_[fm]);
            }
#pragma unroll
            for (int fn = 0; fn < 4; fn++) {
                const uint32_t sw = SWZ64(((uint32_t)(wn * 32 + fn * 8) << 6) +
                                          (uint32_t)(ks * 32) + b_l);
                ldsm2(db + 2 * TILE_B + sw, bh[fn]);
                ldsm2(db + 3 * TILE_B + sw, bl_[fn]);
            }
#pragma unroll
            for (int fm = 0; fm < 4; fm++)
#pragma unroll
                for (int fn = 0; fn < 4; fn++)
                    mma16816(acc[fm][fn], ah[fm], bh[fn]);
#pragma unroll
            for (int fm = 0; fm < 4; fm++)
#pragma unroll
                for (int fn = 0; fn < 4; fn++)
                    mma16816(acc[fm][fn], ah[fm], bl_[fn]);
#pragma unroll
            for (int fm = 0; fm < 4; fm++)
#pragma unroll
                for (int fn = 0; fn < 4; fn++)
                    mma16816(acc[fm][fn], al_[fm], bh[fn]);
        }
        __syncthreads();
        if (it + 2 < nIter) load_tile(it + 2);
    }

    const int er = lane >> 2;
    const int ec = (lane & 3) * 2;
#pragma unroll
    for (int fm = 0; fm < 4; fm++) {
#pragma unroll
        for (int fn = 0; fn < 4; fn++) {
            const int r0 = m0 + wm * 64 + fm * 16 + er;
            const int r1 = r0 + 8;
            const int c  = n0 + wn * 32 + fn * 8 + ec;
            if (EPI == 1) {
                *(float2*)(Of + (size_t)r0 * ldc + c) = make_float2(acc[fm][fn][0], acc[fm][fn][1]);
                *(float2*)(Of + (size_t)r1 * ldc + c) = make_float2(acc[fm][fn][2], acc[fm][fn][3]);
            } else {
#pragma unroll
                for (int p = 0; p < 2; p++) {
                    const int rr = p == 0 ? r0 : r1;
                    const float f0 = acc[fm][fn][2 * p];
                    const float f1 = acc[fm][fn][2 * p + 1];
                    const __nv_bfloat16 h0 = __float2bfloat16(f0);
                    const __nv_bfloat16 h1 = __float2bfloat16(f1);
                    __nv_bfloat162 hv; hv.x = h0; hv.y = h1;
                    __nv_bfloat162 lv;
                    lv.x = __float2bfloat16(f0 - __bfloat162float(h0));
                    lv.y = __float2bfloat16(f1 - __bfloat162float(h1));
                    *(__nv_bfloat162*)(Oh + (size_t)rr * ldc + c) = hv;
                    *(__nv_bfloat162*)(Ol + (size_t)rr * ldc + c) = lv;
                }
            }
        }
    }
}

// ---------------------------------------------------------------------------
// 128x128 NT GEMM tile, single-term TF32 (pre-rounded operands), SW128.
// ---------------------------------------------------------------------------
template <int ROUND>
__device__ __forceinline__ void tf32_core(
    const float* __restrict__ A, int lda,
    const float* __restrict__ B, int ldb,
    int m0, int n0, int nIter,
    float* __restrict__ C, int ldc)
{
    extern __shared__ char smem[];
    const uint32_t sbase = smem_u32(smem);
    const int tid  = threadIdx.x;
    const int lane = tid & 31;
    const int wid  = tid >> 5;
    const int wm   = wid >> 2;
    const int wn   = wid & 3;

    const float* A0 = A + (size_t)m0 * lda;
    const float* B0 = B + (size_t)n0 * ldb;

    auto load_tile = [&](int it) {
        const uint32_t db = sbase + (uint32_t)(it & 1) * PV_STAGE_B;
        const int k0 = it * BK2;
#pragma unroll
        for (int i = 0; i < 4; i++) {
            const int c = tid + i * NTHREADS;
            const int row = c >> 3, ch = c & 7;
            const uint32_t so = SWZ((uint32_t)(row * 128 + ch * 16));
            cp16(db + so,             A0 + (size_t)row * lda + k0 + ch * 4);
            cp16(db + PV_TILE_B + so, B0 + (size_t)row * ldb + k0 + ch * 4);
        }
        cp_commit();
    };

    float acc[4][4][4];
#pragma unroll
    for (int i = 0; i < 4; i++)
#pragma unroll
        for (int j = 0; j < 4; j++)
#pragma unroll
            for (int v = 0; v < 4; v++) acc[i][j][v] = 0.0f;

    load_tile(0);
    load_tile(1);

    const int ar = lane >> 2;
    const int ac = lane & 3;

    for (int it = 0; it < nIter; ++it) {
        if (it + 1 < nIter) cp_wait<1>(); else cp_wait<0>();
        __syncthreads();

        const uint32_t db = sbase + (uint32_t)(it & 1) * PV_STAGE_B;
#pragma unroll
        for (int ks = 0; ks < 4; ks++) {
            const uint32_t c0 = (uint32_t)(ks * 8 + ac) * 4;
            uint32_t a[4][4], bb[4][2];
#pragma unroll
            for (int fm = 0; fm < 4; fm++) {
                const uint32_t r = (uint32_t)(wm * 64 + fm * 16 + ar) * 128;
                a[fm][0] = lds32(db + SWZ(r + c0));
                a[fm][1] = lds32(db + SWZ(r + 1024 + c0));
                a[fm][2] = lds32(db + SWZ(r + c0 + 16));
                a[fm][3] = lds32(db + SWZ(r + 1024 + c0 + 16));
            }
#pragma unroll
            for (int fn = 0; fn < 4; fn++) {
                const uint32_t r = (uint32_t)(wn * 32 + fn * 8 + ar) * 128;
                bb[fn][0] = lds32(db + PV_TILE_B + SWZ(r + c0));
                bb[fn][1] = lds32(db + PV_TILE_B + SWZ(r + c0 + 16));
            }
#pragma unroll
            for (int fm = 0; fm < 4; fm++)
#pragma unroll
                for (int fn = 0; fn < 4; fn++)
                    mma1688t(acc[fm][fn], a[fm], bb[fn]);
        }
        __syncthreads();
        if (it + 2 < nIter) load_tile(it + 2);
    }

    const int er = lane >> 2;
    const int ec = (lane & 3) * 2;
#pragma unroll
    for (int fm = 0; fm < 4; fm++) {
#pragma unroll
        for (int fn = 0; fn < 4; fn++) {
            const int r0 = m0 + wm * 64 + fm * 16 + er;
            const int r1 = r0 + 8;
            const int c  = n0 + wn * 32 + fn * 8 + ec;
            if (ROUND) {
                *(float2*)(C + (size_t)r0 * ldc + c) =
                    make_float2(to_tf32(acc[fm][fn][0]), to_tf32(acc[fm][fn][1]));
                *(float2*)(C + (size_t)r1 * ldc + c) =
                    make_float2(to_tf32(acc[fm][fn][2]), to_tf32(acc[fm][fn][3]));
            } else {
                *(float2*)(C + (size_t)r0 * ldc + c) = make_float2(acc[fm][fn][0], acc[fm][fn][1]);
                *(float2*)(C + (size_t)r1 * ldc + c) = make_float2(acc[fm][fn][2], acc[fm][fn][3]);
            }
        }
    }
}

// ---------------------------------------------------------------------------
// Kernel 0: convert. x -> (xh, xl, xt); wv -> wvt.
// ---------------------------------------------------------------------------
#define NX4 (NTOK * DIM / 4)
#define NW4 (DIM * DIM / 4)

__global__ __launch_bounds__(NTHREADS)
void convert_kernel(const float* __restrict__ x, const float* __restrict__ wv)
{
    const int i = blockIdx.x * NTHREADS + threadIdx.x;
    if (i < NX4) {
        const float4 v = ((const float4*)x)[i];
        const __nv_bfloat16 h0 = __float2bfloat16(v.x), h1 = __float2bfloat16(v.y);
        const __nv_bfloat16 h2 = __float2bfloat16(v.z), h3 = __float2bfloat16(v.w);
        __nv_bfloat162 hv0, hv1, lv0, lv1;
        hv0.x = h0; hv0.y = h1; hv1.x = h2; hv1.y = h3;
        lv0.x = __float2bfloat16(v.x - __bfloat162float(h0));
        lv0.y = __float2bfloat16(v.y - __bfloat162float(h1));
        lv1.x = __float2bfloat16(v.z - __bfloat162float(h2));
        lv1.y = __float2bfloat16(v.w - __bfloat162float(h3));
        ((__nv_bfloat162*)g_xh)[2 * i]     = hv0;
        ((__nv_bfloat162*)g_xh)[2 * i + 1] = hv1;
        ((__nv_bfloat162*)g_xl)[2 * i]     = lv0;
        ((__nv_bfloat162*)g_xl)[2 * i + 1] = lv1;
        ((float4*)g_xt)[i] = make_float4(to_tf32(v.x), to_tf32(v.y),
                                         to_tf32(v.z), to_tf32(v.w));
    } else if (i < NX4 + NW4) {
        const int j = i - NX4;
        const float4 v = ((const float4*)wv)[j];
        ((float4*)g_wvt)[j] = make_float4(to_tf32(v.x), to_tf32(v.y),
                                          to_tf32(v.z), to_tf32(v.w));
    }
}

// ---------------------------------------------------------------------------
// Kernel 1: tiled transpose wq, wk -> bf16 hi/lo pairs of W^T.
// ---------------------------------------------------------------------------
__global__ __launch_bounds__(NTHREADS)
void transpose_w_kernel(const float* __restrict__ wq, const float* __restrict__ wk)
{
    __shared__ float t[32][33];
    const float* src = blockIdx.z ? wk : wq;
    __nv_bfloat16* oh = blockIdx.z ? g_wkTh : g_wqTh;
    __nv_bfloat16* ol = blockIdx.z ? g_wkTl : g_wqTl;
    const int tx = threadIdx.x & 31, ty = threadIdx.x >> 5;
    const int c0 = blockIdx.x * 32, r0 = blockIdx.y * 32;
#pragma unroll
    for (int i = 0; i < 4; i++)
        t[ty + i * 8][tx] = src[(size_t)(r0 + ty + i * 8) * DIM + c0 + tx];
    __syncthreads();
#pragma unroll
    for (int i = 0; i < 4; i++) {
        const int d = c0 + ty + i * 8;
        const int e = r0 + tx;
        const float v = t[tx][ty + i * 8];
        const __nv_bfloat16 h = __float2bfloat16(v);
        oh[(size_t)d * DIM + e] = h;
        ol[(size_t)d * DIM + e] = __float2bfloat16(v - __bfloat162float(h));
    }
}

// ---------------------------------------------------------------------------
// Kernel 2: fused V + M.
// ---------------------------------------------------------------------------
__global__ __launch_bounds__(NTHREADS, 2)
void vm_kernel()
{
    const int cta = blockIdx.x;
    if (cta < 384) {
        const int mi = cta / 64, ni = cta % 64;
        tf32_core<1>(g_wvt, DIM, g_xt, DIM,
                     mi * 128, ni * 128, DIM / BK2, g_vt, NTOK);
    } else {
        const int c2 = cta - 384;
        const int mi = c2 / 6, ni = c2 % 6;
        gemm_core<0>(g_wkTh, g_wkTl, DIM, g_wqTh, g_wqTl, DIM,
                     mi * 128, ni * 128, DIM / BK,
                     g_mh, g_ml, nullptr, DIM);
    }
}

// ---------------------------------------------------------------------------
// Kernel 3: Y = X * Mrow^T (NT, 3-term), bf16 pair out. grid (6, 64).
// ---------------------------------------------------------------------------
__global__ __launch_bounds__(NTHREADS, 2)
void y_kernel()
{
    gemm_core<0>(g_xh, g_xl, DIM, g_mh, g_ml, DIM,
                 blockIdx.y * 128, blockIdx.x * 128, DIM / BK,
                 g_yh, g_yl, nullptr, DIM);
}

// ---------------------------------------------------------------------------
// Kernel 4: scores S = Y X^T, packed lower-triangle grid (136, 4).
// ---------------------------------------------------------------------------
__global__ __launch_bounds__(NTHREADS, 2)
void scores_kernel()
{
    const int t = blockIdx.x;
    int mi = (int)((sqrtf(8.0f * (float)t + 1.0f) - 1.0f) * 0.5f);
    while ((mi + 1) * (mi + 2) / 2 <= t) mi++;
    while (mi * (mi + 1) / 2 > t) mi--;
    const int ni = t - mi * (mi + 1) / 2;

    const int b = blockIdx.y;
    const size_t o = (size_t)b * SEQ * DIM;
    gemm_core<1>(g_yh + o, g_yl + o, DIM,
                 g_xh + o, g_xl + o, DIM,
                 mi * 128, ni * 128, DIM / BK,
                 nullptr, nullptr, g_s + (size_t)b * SEQ * SEQ, SEQ);
}

// ---------------------------------------------------------------------------
// Kernel 5: causal softmax in place (tf32-rounded probs, bounded I/O).
// ---------------------------------------------------------------------------
__global__ __launch_bounds__(NTHREADS)
void softmax_kernel()
{
    const int q = blockIdx.x, b = blockIdx.y;
    float* row = g_s + ((size_t)b * SEQ + q) * SEQ;
    const int nvalid = q + 1;
    const int zlim = (q & ~127) + 128;
    const int tid = threadIdx.x, lane = tid & 31, wid = tid >> 5;

    __shared__ float sred[8];

    const int e0 = 4 * tid, e1 = 4 * (tid + 256);
    float4 v0 = (e0 < nvalid) ? ((const float4*)row)[tid]
                              : make_float4(0.f, 0.f, 0.f, 0.f);
    float4 v1 = (e1 < nvalid) ? ((const float4*)row)[tid + 256]
                              : make_float4(0.f, 0.f, 0.f, 0.f);

    float f[8] = {v0.x, v0.y, v0.z, v0.w, v1.x, v1.y, v1.z, v1.w};
    int   ei[8] = {e0, e0 + 1, e0 + 2, e0 + 3, e1, e1 + 1, e1 + 2, e1 + 3};

    float mx = -INFINITY;
#pragma unroll
    for (int j = 0; j < 8; j++)
        if (ei[j] < nvalid) mx = fmaxf(mx, f[j]);
#pragma unroll
    for (int o = 16; o > 0; o >>= 1)
        mx = fmaxf(mx, __shfl_xor_sync(0xffffffffu, mx, o));
    if (lane == 0) sred[wid] = mx;
    __syncthreads();
    mx = sred[0];
#pragma unroll
    for (int w = 1; w < 8; w++) mx = fmaxf(mx, sred[w]);

    float sum = 0.0f;
#pragma unroll
    for (int j = 0; j < 8; j++) {
        f[j] = (ei[j] < nvalid) ? expf((f[j] - mx) * SCALE) : 0.0f;
        sum += f[j];
    }
#pragma unroll
    for (int o = 16; o > 0; o >>= 1)
        sum += __shfl_xor_sync(0xffffffffu, sum, o);
    __syncthreads();
    if (lane == 0) sred[wid] = sum;
    __syncthreads();
    sum = 0.0f;
#pragma unroll
    for (int w = 0; w < 8; w++) sum += sred[w];
    const float inv = 1.0f / sum;

    if (e0 < zlim)
        ((float4*)row)[tid] = make_float4(to_tf32(f[0] * inv), to_tf32(f[1] * inv),
                                          to_tf32(f[2] * inv), to_tf32(f[3] * inv));
    if (e1 < zlim)
        ((float4*)row)[tid + 256] = make_float4(to_tf32(f[4] * inv), to_tf32(f[5] * inv),
                                                to_tf32(f[6] * inv), to_tf32(f[7] * inv));
}

// ---------------------------------------------------------------------------
// Kernel 6: O = P V via V^T, single-term tf32, k bounded by causal diagonal.
// ---------------------------------------------------------------------------
__global__ __launch_bounds__(NTHREADS, 2)
void pv_kernel(float* __restrict__ out)
{
    const int b = blockIdx.z;
    const int m0 = blockIdx.y * 128, n0 = blockIdx.x * 128;
    tf32_core<0>(g_s + (size_t)b * SEQ * SEQ, SEQ,
                 g_vt + (size_t)b * SEQ, NTOK,
                 m0, n0, (m0 + 128) / BK2,
                 out + (size_t)b * SEQ * DIM, DIM);
}

// ---------------------------------------------------------------------------
extern "C" void kernel_launch(void* const* d_in, const int* in_sizes, int n_in,
                              void* d_out, int out_size)
{
    const float* x  = (const float*)d_in[0];
    const float* wq = (const float*)d_in[1];
    const float* wk = (const float*)d_in[2];
    const float* wv = (const float*)d_in[3];
    float* out = (float*)d_out;

    cudaFuncSetAttribute(vm_kernel,     cudaFuncAttributeMaxDynamicSharedMemorySize, PV_SMEM);
    cudaFuncSetAttribute(y_kernel,      cudaFuncAttributeMaxDynamicSharedMemorySize, SMEM_BYTES);
    cudaFuncSetAttribute(scores_kernel, cudaFuncAttributeMaxDynamicSharedMemorySize, SMEM_BYTES);
    cudaFuncSetAttribute(pv_kernel,     cudaFuncAttributeMaxDynamicSharedMemorySize, PV_SMEM);

    const int ntot = NX4 + NW4;
    convert_kernel<<<(ntot + NTHREADS - 1) / NTHREADS, NTHREADS>>>(x, wv);
    transpose_w_kernel<<<dim3(24, 24, 2), NTHREADS>>>(wq, wk);
    vm_kernel<<<420, NTHREADS, PV_SMEM>>>();
    y_kernel<<<dim3(DIM / 128, NTOK / 128), NTHREADS, SMEM_BYTES>>>();
    scores_kernel<<<dim3(136, BATCH), NTHREADS, SMEM_BYTES>>>();
    softmax_kernel<<<dim3(SEQ, BATCH), NTHREADS>>>();
    pv_kernel<<<dim3(DIM / 128, SEQ / 128, BATCH), NTHREADS, PV_SMEM>>>(out);
}

// round 8
// speedup vs baseline: 4.0027x; 1.0610x over previous
#include <cuda_runtime.h>
#include <cuda_bf16.h>
#include <math.h>
#include <stdint.h>

// ---------------------------------------------------------------------------
// Problem constants
// ---------------------------------------------------------------------------
#define BATCH 4
#define SEQ   2048
#define DIM   768
#define NTOK  (BATCH * SEQ)          // 8192
#define NTHREADS 256
#define SCALE 0.03608439182435161f   // 1/sqrt(768)

// bf16 GEMM tiling: 128x128 CTA tile, K chunk of 32 bf16 (64B rows, SW64)
#define BK 32
#define TILE_B  8192
#define STAGE_B (4 * TILE_B)         // 32 KB
#define SMEM_BYTES (2 * STAGE_B)     // 64 KB

// tf32 tiling: 128x128 CTA tile, K chunk of 32 fp32 (128B rows, SW128)
#define BK2 32
#define PV_TILE_B  16384
#define PV_STAGE_B (2 * PV_TILE_B)
#define PV_SMEM    (2 * PV_STAGE_B)  // 64 KB

#define SWZ(o)   ((o) ^ ((((uint32_t)(o)) >> 3) & 0x70))   // SW128
#define SWZ64(o) ((o) ^ ((((uint32_t)(o)) >> 3) & 0x30))   // SW64

// ---------------------------------------------------------------------------
// Scratch (__device__ globals; referenced ONLY from device code)
// ---------------------------------------------------------------------------
__device__ __align__(128) __nv_bfloat16 g_xh[NTOK * DIM], g_xl[NTOK * DIM];
__device__ __align__(128) float         g_xt[NTOK * DIM];
__device__ __align__(128) __nv_bfloat16 g_wqTh[DIM * DIM], g_wqTl[DIM * DIM];
__device__ __align__(128) __nv_bfloat16 g_wkTh[DIM * DIM], g_wkTl[DIM * DIM];
__device__ __align__(128) float         g_wvt[DIM * DIM];
__device__ __align__(128) __nv_bfloat16 g_mh[DIM * DIM], g_ml[DIM * DIM];
__device__ __align__(128) float         g_yt[NTOK * DIM];   // Y tf32-rounded fp32
__device__ __align__(128) float         g_vt[DIM * NTOK];
__device__ __align__(128) float         g_s[(size_t)BATCH * SEQ * SEQ];

// ---------------------------------------------------------------------------
// PTX helpers
// ---------------------------------------------------------------------------
__device__ __forceinline__ uint32_t smem_u32(const void* p) {
    uint32_t a;
    asm("{ .reg .u64 t; cvta.to.shared.u64 t, %1; cvt.u32.u64 %0, t; }"
        : "=r"(a) : "l"(p));
    return a;
}
__device__ __forceinline__ void cp16(uint32_t dst, const void* src) {
    asm volatile("cp.async.cg.shared.global [%0], [%1], 16;" :: "r"(dst), "l"(src));
}
__device__ __forceinline__ void cp_commit() {
    asm volatile("cp.async.commit_group;" ::: "memory");
}
template <int N>
__device__ __forceinline__ void cp_wait() {
    asm volatile("cp.async.wait_group %0;" :: "n"(N) : "memory");
}
__device__ __forceinline__ void ldsm4(uint32_t addr, uint32_t* r) {
    asm volatile("ldmatrix.sync.aligned.m8n8.x4.shared.b16 {%0,%1,%2,%3}, [%4];"
                 : "=r"(r[0]), "=r"(r[1]), "=r"(r[2]), "=r"(r[3]) : "r"(addr));
}
__device__ __forceinline__ void ldsm2(uint32_t addr, uint32_t* r) {
    asm volatile("ldmatrix.sync.aligned.m8n8.x2.shared.b16 {%0,%1}, [%2];"
                 : "=r"(r[0]), "=r"(r[1]) : "r"(addr));
}
__device__ __forceinline__ void mma16816(float* d, const uint32_t* a, const uint32_t* b) {
    asm volatile(
        "mma.sync.aligned.m16n8k16.row.col.f32.bf16.bf16.f32 "
        "{%0,%1,%2,%3}, {%4,%5,%6,%7}, {%8,%9}, {%0,%1,%2,%3};"
        : "+f"(d[0]), "+f"(d[1]), "+f"(d[2]), "+f"(d[3])
        : "r"(a[0]), "r"(a[1]), "r"(a[2]), "r"(a[3]), "r"(b[0]), "r"(b[1]));
}
__device__ __forceinline__ void mma1688t(float* d, const uint32_t* a, const uint32_t* b) {
    asm volatile(
        "mma.sync.aligned.m16n8k8.row.col.f32.tf32.tf32.f32 "
        "{%0,%1,%2,%3}, {%4,%5,%6,%7}, {%8,%9}, {%0,%1,%2,%3};"
        : "+f"(d[0]), "+f"(d[1]), "+f"(d[2]), "+f"(d[3])
        : "r"(a[0]), "r"(a[1]), "r"(a[2]), "r"(a[3]), "r"(b[0]), "r"(b[1]));
}
__device__ __forceinline__ uint32_t lds32(uint32_t addr) {
    uint32_t v;
    asm volatile("ld.shared.b32 %0, [%1];" : "=r"(v) : "r"(addr));
    return v;
}
__device__ __forceinline__ float to_tf32(float x) {
    float r;
    asm("cvt.rna.tf32.f32 %0, %1;" : "=f"(r) : "f"(x));
    return r;
}

// ---------------------------------------------------------------------------
// 128x128 NT GEMM tile, split-bf16 3-term, BK=32, SW64.
// EPI 0: bf16 hi/lo pair out.  EPI 1: fp32 out.  EPI 2: tf32-rounded fp32 out.
// ---------------------------------------------------------------------------
template <int EPI>
__device__ __forceinline__ void gemm_core(
    const __nv_bfloat16* __restrict__ Ah, const __nv_bfloat16* __restrict__ Al, int lda,
    const __nv_bfloat16* __restrict__ Bh, const __nv_bfloat16* __restrict__ Bl, int ldb,
    int m0, int n0, int nIter,
    __nv_bfloat16* __restrict__ Oh, __nv_bfloat16* __restrict__ Ol,
    float* __restrict__ Of, int ldc)
{
    extern __shared__ char smem[];
    const uint32_t sbase = smem_u32(smem);
    const int tid  = threadIdx.x;
    const int lane = tid & 31;
    const int wid  = tid >> 5;
    const int wm   = wid >> 2;
    const int wn   = wid & 3;

    const __nv_bfloat16* A0h = Ah + (size_t)m0 * lda;
    const __nv_bfloat16* A0l = Al + (size_t)m0 * lda;
    const __nv_bfloat16* B0h = Bh + (size_t)n0 * ldb;
    const __nv_bfloat16* B0l = Bl + (size_t)n0 * ldb;

    auto load_tile = [&](int it) {
        const uint32_t db = sbase + (uint32_t)(it & 1) * STAGE_B;
        const int k0 = it * BK;
#pragma unroll
        for (int i = 0; i < 2; i++) {
            const int c = tid + i * NTHREADS;
            const int row = c >> 2, ch = c & 3;
            const uint32_t so = SWZ64((uint32_t)(row * 64 + ch * 16));
            const size_t ga = (size_t)row * lda + k0 + ch * 8;
            const size_t gb = (size_t)row * ldb + k0 + ch * 8;
            cp16(db + so,              A0h + ga);
            cp16(db + TILE_B + so,     A0l + ga);
            cp16(db + 2 * TILE_B + so, B0h + gb);
            cp16(db + 3 * TILE_B + so, B0l + gb);
        }
        cp_commit();
    };

    float acc[4][4][4];
#pragma unroll
    for (int i = 0; i < 4; i++)
#pragma unroll
        for (int j = 0; j < 4; j++)
#pragma unroll
            for (int v = 0; v < 4; v++) acc[i][j][v] = 0.0f;

    const uint32_t a_l = ((uint32_t)(lane & 15) << 6) + ((uint32_t)(lane >> 4) << 4);
    const uint32_t b_l = ((uint32_t)(lane & 7) << 6) + ((uint32_t)((lane >> 3) & 1) << 4);

    load_tile(0);
    load_tile(1);

    for (int it = 0; it < nIter; ++it) {
        if (it + 1 < nIter) cp_wait<1>(); else cp_wait<0>();
        __syncthreads();

        const uint32_t db = sbase + (uint32_t)(it & 1) * STAGE_B;
#pragma unroll
        for (int ks = 0; ks < 2; ks++) {
            uint32_t ah[4][4], al_[4][4], bh[4][2], bl_[4][2];
#pragma unroll
            for (int fm = 0; fm < 4; fm++) {
                const uint32_t sw = SWZ64(((uint32_t)(wm * 64 + fm * 16) << 6) +
                                          (uint32_t)(ks * 32) + a_l);
                ldsm4(db + sw, ah[fm]);
                ldsm4(db + TILE_B + sw, al_[fm]);
            }
#pragma unroll
            for (int fn = 0; fn < 4; fn++) {
                const uint32_t sw = SWZ64(((uint32_t)(wn * 32 + fn * 8) << 6) +
                                          (uint32_t)(ks * 32) + b_l);
                ldsm2(db + 2 * TILE_B + sw, bh[fn]);
                ldsm2(db + 3 * TILE_B + sw, bl_[fn]);
            }
#pragma unroll
            for (int fm = 0; fm < 4; fm++)
#pragma unroll
                for (int fn = 0; fn < 4; fn++)
                    mma16816(acc[fm][fn], ah[fm], bh[fn]);
#pragma unroll
            for (int fm = 0; fm < 4; fm++)
#pragma unroll
                for (int fn = 0; fn < 4; fn++)
                    mma16816(acc[fm][fn], ah[fm], bl_[fn]);
#pragma unroll
            for (int fm = 0; fm < 4; fm++)
#pragma unroll
                for (int fn = 0; fn < 4; fn++)
                    mma16816(acc[fm][fn], al_[fm], bh[fn]);
        }
        __syncthreads();
        if (it + 2 < nIter) load_tile(it + 2);
    }

    const int er = lane >> 2;
    const int ec = (lane & 3) * 2;
#pragma unroll
    for (int fm = 0; fm < 4; fm++) {
#pragma unroll
        for (int fn = 0; fn < 4; fn++) {
            const int r0 = m0 + wm * 64 + fm * 16 + er;
            const int r1 = r0 + 8;
            const int c  = n0 + wn * 32 + fn * 8 + ec;
            if (EPI == 1) {
                *(float2*)(Of + (size_t)r0 * ldc + c) = make_float2(acc[fm][fn][0], acc[fm][fn][1]);
                *(float2*)(Of + (size_t)r1 * ldc + c) = make_float2(acc[fm][fn][2], acc[fm][fn][3]);
            } else if (EPI == 2) {
                *(float2*)(Of + (size_t)r0 * ldc + c) =
                    make_float2(to_tf32(acc[fm][fn][0]), to_tf32(acc[fm][fn][1]));
                *(float2*)(Of + (size_t)r1 * ldc + c) =
                    make_float2(to_tf32(acc[fm][fn][2]), to_tf32(acc[fm][fn][3]));
            } else {
#pragma unroll
                for (int p = 0; p < 2; p++) {
                    const int rr = p == 0 ? r0 : r1;
                    const float f0 = acc[fm][fn][2 * p];
                    const float f1 = acc[fm][fn][2 * p + 1];
                    const __nv_bfloat16 h0 = __float2bfloat16(f0);
                    const __nv_bfloat16 h1 = __float2bfloat16(f1);
                    __nv_bfloat162 hv; hv.x = h0; hv.y = h1;
                    __nv_bfloat162 lv;
                    lv.x = __float2bfloat16(f0 - __bfloat162float(h0));
                    lv.y = __float2bfloat16(f1 - __bfloat162float(h1));
                    *(__nv_bfloat162*)(Oh + (size_t)rr * ldc + c) = hv;
                    *(__nv_bfloat162*)(Ol + (size_t)rr * ldc + c) = lv;
                }
            }
        }
    }
}

// ---------------------------------------------------------------------------
// 128x128 NT GEMM tile, single-term TF32 (pre-rounded operands), SW128.
// ---------------------------------------------------------------------------
template <int ROUND>
__device__ __forceinline__ void tf32_core(
    const float* __restrict__ A, int lda,
    const float* __restrict__ B, int ldb,
    int m0, int n0, int nIter,
    float* __restrict__ C, int ldc)
{
    extern __shared__ char smem[];
    const uint32_t sbase = smem_u32(smem);
    const int tid  = threadIdx.x;
    const int lane = tid & 31;
    const int wid  = tid >> 5;
    const int wm   = wid >> 2;
    const int wn   = wid & 3;

    const float* A0 = A + (size_t)m0 * lda;
    const float* B0 = B + (size_t)n0 * ldb;

    auto load_tile = [&](int it) {
        const uint32_t db = sbase + (uint32_t)(it & 1) * PV_STAGE_B;
        const int k0 = it * BK2;
#pragma unroll
        for (int i = 0; i < 4; i++) {
            const int c = tid + i * NTHREADS;
            const int row = c >> 3, ch = c & 7;
            const uint32_t so = SWZ((uint32_t)(row * 128 + ch * 16));
            cp16(db + so,             A0 + (size_t)row * lda + k0 + ch * 4);
            cp16(db + PV_TILE_B + so, B0 + (size_t)row * ldb + k0 + ch * 4);
        }
        cp_commit();
    };

    float acc[4][4][4];
#pragma unroll
    for (int i = 0; i < 4; i++)
#pragma unroll
        for (int j = 0; j < 4; j++)
#pragma unroll
            for (int v = 0; v < 4; v++) acc[i][j][v] = 0.0f;

    load_tile(0);
    load_tile(1);

    const int ar = lane >> 2;
    const int ac = lane & 3;

    for (int it = 0; it < nIter; ++it) {
        if (it + 1 < nIter) cp_wait<1>(); else cp_wait<0>();
        __syncthreads();

        const uint32_t db = sbase + (uint32_t)(it & 1) * PV_STAGE_B;
#pragma unroll
        for (int ks = 0; ks < 4; ks++) {
            const uint32_t c0 = (uint32_t)(ks * 8 + ac) * 4;
            uint32_t a[4][4], bb[4][2];
#pragma unroll
            for (int fm = 0; fm < 4; fm++) {
                const uint32_t r = (uint32_t)(wm * 64 + fm * 16 + ar) * 128;
                a[fm][0] = lds32(db + SWZ(r + c0));
                a[fm][1] = lds32(db + SWZ(r + 1024 + c0));
                a[fm][2] = lds32(db + SWZ(r + c0 + 16));
                a[fm][3] = lds32(db + SWZ(r + 1024 + c0 + 16));
            }
#pragma unroll
            for (int fn = 0; fn < 4; fn++) {
                const uint32_t r = (uint32_t)(wn * 32 + fn * 8 + ar) * 128;
                bb[fn][0] = lds32(db + PV_TILE_B + SWZ(r + c0));
                bb[fn][1] = lds32(db + PV_TILE_B + SWZ(r + c0 + 16));
            }
#pragma unroll
            for (int fm = 0; fm < 4; fm++)
#pragma unroll
                for (int fn = 0; fn < 4; fn++)
                    mma1688t(acc[fm][fn], a[fm], bb[fn]);
        }
        __syncthreads();
        if (it + 2 < nIter) load_tile(it + 2);
    }

    const int er = lane >> 2;
    const int ec = (lane & 3) * 2;
#pragma unroll
    for (int fm = 0; fm < 4; fm++) {
#pragma unroll
        for (int fn = 0; fn < 4; fn++) {
            const int r0 = m0 + wm * 64 + fm * 16 + er;
            const int r1 = r0 + 8;
            const int c  = n0 + wn * 32 + fn * 8 + ec;
            if (ROUND) {
                *(float2*)(C + (size_t)r0 * ldc + c) =
                    make_float2(to_tf32(acc[fm][fn][0]), to_tf32(acc[fm][fn][1]));
                *(float2*)(C + (size_t)r1 * ldc + c) =
                    make_float2(to_tf32(acc[fm][fn][2]), to_tf32(acc[fm][fn][3]));
            } else {
                *(float2*)(C + (size_t)r0 * ldc + c) = make_float2(acc[fm][fn][0], acc[fm][fn][1]);
                *(float2*)(C + (size_t)r1 * ldc + c) = make_float2(acc[fm][fn][2], acc[fm][fn][3]);
            }
        }
    }
}

// ---------------------------------------------------------------------------
// Kernel 0: convert. x -> (xh, xl, xt); wv -> wvt.
// ---------------------------------------------------------------------------
#define NX4 (NTOK * DIM / 4)
#define NW4 (DIM * DIM / 4)

__global__ __launch_bounds__(NTHREADS)
void convert_kernel(const float* __restrict__ x, const float* __restrict__ wv)
{
    const int i = blockIdx.x * NTHREADS + threadIdx.x;
    if (i < NX4) {
        const float4 v = ((const float4*)x)[i];
        const __nv_bfloat16 h0 = __float2bfloat16(v.x), h1 = __float2bfloat16(v.y);
        const __nv_bfloat16 h2 = __float2bfloat16(v.z), h3 = __float2bfloat16(v.w);
        __nv_bfloat162 hv0, hv1, lv0, lv1;
        hv0.x = h0; hv0.y = h1; hv1.x = h2; hv1.y = h3;
        lv0.x = __float2bfloat16(v.x - __bfloat162float(h0));
        lv0.y = __float2bfloat16(v.y - __bfloat162float(h1));
        lv1.x = __float2bfloat16(v.z - __bfloat162float(h2));
        lv1.y = __float2bfloat16(v.w - __bfloat162float(h3));
        ((__nv_bfloat162*)g_xh)[2 * i]     = hv0;
        ((__nv_bfloat162*)g_xh)[2 * i + 1] = hv1;
        ((__nv_bfloat162*)g_xl)[2 * i]     = lv0;
        ((__nv_bfloat162*)g_xl)[2 * i + 1] = lv1;
        ((float4*)g_xt)[i] = make_float4(to_tf32(v.x), to_tf32(v.y),
                                         to_tf32(v.z), to_tf32(v.w));
    } else if (i < NX4 + NW4) {
        const int j = i - NX4;
        const float4 v = ((const float4*)wv)[j];
        ((float4*)g_wvt)[j] = make_float4(to_tf32(v.x), to_tf32(v.y),
                                          to_tf32(v.z), to_tf32(v.w));
    }
}

// ---------------------------------------------------------------------------
// Kernel 1: tiled transpose wq, wk -> bf16 hi/lo pairs of W^T.
// ---------------------------------------------------------------------------
__global__ __launch_bounds__(NTHREADS)
void transpose_w_kernel(const float* __restrict__ wq, const float* __restrict__ wk)
{
    __shared__ float t[32][33];
    const float* src = blockIdx.z ? wk : wq;
    __nv_bfloat16* oh = blockIdx.z ? g_wkTh : g_wqTh;
    __nv_bfloat16* ol = blockIdx.z ? g_wkTl : g_wqTl;
    const int tx = threadIdx.x & 31, ty = threadIdx.x >> 5;
    const int c0 = blockIdx.x * 32, r0 = blockIdx.y * 32;
#pragma unroll
    for (int i = 0; i < 4; i++)
        t[ty + i * 8][tx] = src[(size_t)(r0 + ty + i * 8) * DIM + c0 + tx];
    __syncthreads();
#pragma unroll
    for (int i = 0; i < 4; i++) {
        const int d = c0 + ty + i * 8;
        const int e = r0 + tx;
        const float v = t[tx][ty + i * 8];
        const __nv_bfloat16 h = __float2bfloat16(v);
        oh[(size_t)d * DIM + e] = h;
        ol[(size_t)d * DIM + e] = __float2bfloat16(v - __bfloat162float(h));
    }
}

// ---------------------------------------------------------------------------
// Kernel 2: fused V + M.
// ---------------------------------------------------------------------------
__global__ __launch_bounds__(NTHREADS, 2)
void vm_kernel()
{
    const int cta = blockIdx.x;
    if (cta < 384) {
        const int mi = cta / 64, ni = cta % 64;
        tf32_core<1>(g_wvt, DIM, g_xt, DIM,
                     mi * 128, ni * 128, DIM / BK2, g_vt, NTOK);
    } else {
        const int c2 = cta - 384;
        const int mi = c2 / 6, ni = c2 % 6;
        gemm_core<0>(g_wkTh, g_wkTl, DIM, g_wqTh, g_wqTl, DIM,
                     mi * 128, ni * 128, DIM / BK,
                     g_mh, g_ml, nullptr, DIM);
    }
}

// ---------------------------------------------------------------------------
// Kernel 3: Y = X * Mrow^T (NT, 3-term bf16), tf32-rounded fp32 out.
// ---------------------------------------------------------------------------
__global__ __launch_bounds__(NTHREADS, 2)
void y_kernel()
{
    gemm_core<2>(g_xh, g_xl, DIM, g_mh, g_ml, DIM,
                 blockIdx.y * 128, blockIdx.x * 128, DIM / BK,
                 nullptr, nullptr, g_yt, DIM);
}

// ---------------------------------------------------------------------------
// Kernel 4: scores S = Y X^T, single-term TF32, packed triangle grid (136,4).
// ---------------------------------------------------------------------------
__global__ __launch_bounds__(NTHREADS, 2)
void scores_kernel()
{
    const int t = blockIdx.x;
    int mi = (int)((sqrtf(8.0f * (float)t + 1.0f) - 1.0f) * 0.5f);
    while ((mi + 1) * (mi + 2) / 2 <= t) mi++;
    while (mi * (mi + 1) / 2 > t) mi--;
    const int ni = t - mi * (mi + 1) / 2;

    const int b = blockIdx.y;
    const size_t o = (size_t)b * SEQ * DIM;
    tf32_core<0>(g_yt + o, DIM, g_xt + o, DIM,
                 mi * 128, ni * 128, DIM / BK2,
                 g_s + (size_t)b * SEQ * SEQ, SEQ);
}

// ---------------------------------------------------------------------------
// Kernel 5: causal softmax in place (tf32-rounded probs, bounded I/O).
// ---------------------------------------------------------------------------
__global__ __launch_bounds__(NTHREADS)
void softmax_kernel()
{
    const int q = blockIdx.x, b = blockIdx.y;
    float* row = g_s + ((size_t)b * SEQ + q) * SEQ;
    const int nvalid = q + 1;
    const int zlim = (q & ~127) + 128;
    const int tid = threadIdx.x, lane = tid & 31, wid = tid >> 5;

    __shared__ float sred[8];

    const int e0 = 4 * tid, e1 = 4 * (tid + 256);
    float4 v0 = (e0 < nvalid) ? ((const float4*)row)[tid]
                              : make_float4(0.f, 0.f, 0.f, 0.f);
    float4 v1 = (e1 < nvalid) ? ((const float4*)row)[tid + 256]
                              : make_float4(0.f, 0.f, 0.f, 0.f);

    float f[8] = {v0.x, v0.y, v0.z, v0.w, v1.x, v1.y, v1.z, v1.w};
    int   ei[8] = {e0, e0 + 1, e0 + 2, e0 + 3, e1, e1 + 1, e1 + 2, e1 + 3};

    float mx = -INFINITY;
#pragma unroll
    for (int j = 0; j < 8; j++)
        if (ei[j] < nvalid) mx = fmaxf(mx, f[j]);
#pragma unroll
    for (int o = 16; o > 0; o >>= 1)
        mx = fmaxf(mx, __shfl_xor_sync(0xffffffffu, mx, o));
    if (lane == 0) sred[wid] = mx;
    __syncthreads();
    mx = sred[0];
#pragma unroll
    for (int w = 1; w < 8; w++) mx = fmaxf(mx, sred[w]);

    float sum = 0.0f;
#pragma unroll
    for (int j = 0; j < 8; j++) {
        f[j] = (ei[j] < nvalid) ? expf((f[j] - mx) * SCALE) : 0.0f;
        sum += f[j];
    }
#pragma unroll
    for (int o = 16; o > 0; o >>= 1)
        sum += __shfl_xor_sync(0xffffffffu, sum, o);
    __syncthreads();
    if (lane == 0) sred[wid] = sum;
    __syncthreads();
    sum = 0.0f;
#pragma unroll
    for (int w = 0; w < 8; w++) sum += sred[w];
    const float inv = 1.0f / sum;

    if (e0 < zlim)
        ((float4*)row)[tid] = make_float4(to_tf32(f[0] * inv), to_tf32(f[1] * inv),
                                          to_tf32(f[2] * inv), to_tf32(f[3] * inv));
    if (e1 < zlim)
        ((float4*)row)[tid + 256] = make_float4(to_tf32(f[4] * inv), to_tf32(f[5] * inv),
                                                to_tf32(f[6] * inv), to_tf32(f[7] * inv));
}

// ---------------------------------------------------------------------------
// Kernel 6: O = P V via V^T, single-term tf32, k bounded by causal diagonal.
// ---------------------------------------------------------------------------
__global__ __launch_bounds__(NTHREADS, 2)
void pv_kernel(float* __restrict__ out)
{
    const int b = blockIdx.z;
    const int m0 = blockIdx.y * 128, n0 = blockIdx.x * 128;
    tf32_core<0>(g_s + (size_t)b * SEQ * SEQ, SEQ,
                 g_vt + (size_t)b * SEQ, NTOK,
                 m0, n0, (m0 + 128) / BK2,
                 out + (size_t)b * SEQ * DIM, DIM);
}

// ---------------------------------------------------------------------------
extern "C" void kernel_launch(void* const* d_in, const int* in_sizes, int n_in,
                              void* d_out, int out_size)
{
    const float* x  = (const float*)d_in[0];
    const float* wq = (const float*)d_in[1];
    const float* wk = (const float*)d_in[2];
    const float* wv = (const float*)d_in[3];
    float* out = (float*)d_out;

    cudaFuncSetAttribute(vm_kernel,     cudaFuncAttributeMaxDynamicSharedMemorySize, PV_SMEM);
    cudaFuncSetAttribute(y_kernel,      cudaFuncAttributeMaxDynamicSharedMemorySize, SMEM_BYTES);
    cudaFuncSetAttribute(scores_kernel, cudaFuncAttributeMaxDynamicSharedMemorySize, PV_SMEM);
    cudaFuncSetAttribute(pv_kernel,     cudaFuncAttributeMaxDynamicSharedMemorySize, PV_SMEM);

    const int ntot = NX4 + NW4;
    convert_kernel<<<(ntot + NTHREADS - 1) / NTHREADS, NTHREADS>>>(x, wv);
    transpose_w_kernel<<<dim3(24, 24, 2), NTHREADS>>>(wq, wk);
    vm_kernel<<<420, NTHREADS, PV_SMEM>>>();
    y_kernel<<<dim3(DIM / 128, NTOK / 128), NTHREADS, SMEM_BYTES>>>();
    scores_kernel<<<dim3(136, BATCH), NTHREADS, PV_SMEM>>>();
    softmax_kernel<<<dim3(SEQ, BATCH), NTHREADS>>>();
    pv_kernel<<<dim3(DIM / 128, SEQ / 128, BATCH), NTHREADS, PV_SMEM>>>(out);
}

// round 9
// speedup vs baseline: 4.2045x; 1.0504x over previous
#include <cuda_runtime.h>
#include <cuda_bf16.h>
#include <math.h>
#include <stdint.h>

// ---------------------------------------------------------------------------
// Problem constants
// ---------------------------------------------------------------------------
#define BATCH 4
#define SEQ   2048
#define DIM   768
#define NTOK  (BATCH * SEQ)          // 8192
#define NTHREADS 256
#define SCALE 0.03608439182435161f   // 1/sqrt(768)

// bf16 GEMM tiling (M GEMM only): 128x128 tile, K chunk 32 bf16, SW64
#define BK 32
#define TILE_B  8192
#define STAGE_B (4 * TILE_B)         // 32 KB
#define SMEM_BYTES (2 * STAGE_B)     // 64 KB

// tf32 tiling: 128x128 CTA tile, K chunk of 32 fp32 (128B rows, SW128)
#define BK2 32
#define PV_TILE_B  16384
#define PV_STAGE_B (2 * PV_TILE_B)
#define PV_SMEM    (2 * PV_STAGE_B)  // 64 KB

#define SWZ(o)   ((o) ^ ((((uint32_t)(o)) >> 3) & 0x70))   // SW128
#define SWZ64(o) ((o) ^ ((((uint32_t)(o)) >> 3) & 0x30))   // SW64

// ---------------------------------------------------------------------------
// Scratch (__device__ globals; referenced ONLY from device code)
// ---------------------------------------------------------------------------
__device__ __align__(128) float         g_xt[NTOK * DIM];      // x tf32-rounded
__device__ __align__(128) __nv_bfloat16 g_wqTh[DIM * DIM], g_wqTl[DIM * DIM];
__device__ __align__(128) __nv_bfloat16 g_wkTh[DIM * DIM], g_wkTl[DIM * DIM];
__device__ __align__(128) float         g_wvt[DIM * DIM];      // wv tf32-rounded
__device__ __align__(128) float         g_mt[DIM * DIM];       // Mrow tf32-rounded
__device__ __align__(128) float         g_yt[NTOK * DIM];      // Y tf32-rounded
__device__ __align__(128) float         g_vt[DIM * NTOK];      // V^T tf32-rounded
__device__ __align__(128) float         g_s[(size_t)BATCH * SEQ * SEQ];

// ---------------------------------------------------------------------------
// PTX helpers
// ---------------------------------------------------------------------------
__device__ __forceinline__ uint32_t smem_u32(const void* p) {
    uint32_t a;
    asm("{ .reg .u64 t; cvta.to.shared.u64 t, %1; cvt.u32.u64 %0, t; }"
        : "=r"(a) : "l"(p));
    return a;
}
__device__ __forceinline__ void cp16(uint32_t dst, const void* src) {
    asm volatile("cp.async.cg.shared.global [%0], [%1], 16;" :: "r"(dst), "l"(src));
}
__device__ __forceinline__ void cp_commit() {
    asm volatile("cp.async.commit_group;" ::: "memory");
}
template <int N>
__device__ __forceinline__ void cp_wait() {
    asm volatile("cp.async.wait_group %0;" :: "n"(N) : "memory");
}
__device__ __forceinline__ void ldsm4(uint32_t addr, uint32_t* r) {
    asm volatile("ldmatrix.sync.aligned.m8n8.x4.shared.b16 {%0,%1,%2,%3}, [%4];"
                 : "=r"(r[0]), "=r"(r[1]), "=r"(r[2]), "=r"(r[3]) : "r"(addr));
}
__device__ __forceinline__ void ldsm2(uint32_t addr, uint32_t* r) {
    asm volatile("ldmatrix.sync.aligned.m8n8.x2.shared.b16 {%0,%1}, [%2];"
                 : "=r"(r[0]), "=r"(r[1]) : "r"(addr));
}
__device__ __forceinline__ void mma16816(float* d, const uint32_t* a, const uint32_t* b) {
    asm volatile(
        "mma.sync.aligned.m16n8k16.row.col.f32.bf16.bf16.f32 "
        "{%0,%1,%2,%3}, {%4,%5,%6,%7}, {%8,%9}, {%0,%1,%2,%3};"
        : "+f"(d[0]), "+f"(d[1]), "+f"(d[2]), "+f"(d[3])
        : "r"(a[0]), "r"(a[1]), "r"(a[2]), "r"(a[3]), "r"(b[0]), "r"(b[1]));
}
__device__ __forceinline__ void mma1688t(float* d, const uint32_t* a, const uint32_t* b) {
    asm volatile(
        "mma.sync.aligned.m16n8k8.row.col.f32.tf32.tf32.f32 "
        "{%0,%1,%2,%3}, {%4,%5,%6,%7}, {%8,%9}, {%0,%1,%2,%3};"
        : "+f"(d[0]), "+f"(d[1]), "+f"(d[2]), "+f"(d[3])
        : "r"(a[0]), "r"(a[1]), "r"(a[2]), "r"(a[3]), "r"(b[0]), "r"(b[1]));
}
__device__ __forceinline__ uint32_t lds32(uint32_t addr) {
    uint32_t v;
    asm volatile("ld.shared.b32 %0, [%1];" : "=r"(v) : "r"(addr));
    return v;
}
__device__ __forceinline__ float to_tf32(float x) {
    float r;
    asm("cvt.rna.tf32.f32 %0, %1;" : "=f"(r) : "f"(x));
    return r;
}

// ---------------------------------------------------------------------------
// 128x128 NT GEMM tile, split-bf16 3-term, BK=32, SW64.
// Used ONLY for the tiny M GEMM now. EPI 2: tf32-rounded fp32 out.
// ---------------------------------------------------------------------------
__device__ __forceinline__ void gemm_core_m(
    const __nv_bfloat16* __restrict__ Ah, const __nv_bfloat16* __restrict__ Al, int lda,
    const __nv_bfloat16* __restrict__ Bh, const __nv_bfloat16* __restrict__ Bl, int ldb,
    int m0, int n0, int nIter,
    float* __restrict__ Of, int ldc)
{
    extern __shared__ char smem[];
    const uint32_t sbase = smem_u32(smem);
    const int tid  = threadIdx.x;
    const int lane = tid & 31;
    const int wid  = tid >> 5;
    const int wm   = wid >> 2;
    const int wn   = wid & 3;

    const __nv_bfloat16* A0h = Ah + (size_t)m0 * lda;
    const __nv_bfloat16* A0l = Al + (size_t)m0 * lda;
    const __nv_bfloat16* B0h = Bh + (size_t)n0 * ldb;
    const __nv_bfloat16* B0l = Bl + (size_t)n0 * ldb;

    auto load_tile = [&](int it) {
        const uint32_t db = sbase + (uint32_t)(it & 1) * STAGE_B;
        const int k0 = it * BK;
#pragma unroll
        for (int i = 0; i < 2; i++) {
            const int c = tid + i * NTHREADS;
            const int row = c >> 2, ch = c & 3;
            const uint32_t so = SWZ64((uint32_t)(row * 64 + ch * 16));
            const size_t ga = (size_t)row * lda + k0 + ch * 8;
            const size_t gb = (size_t)row * ldb + k0 + ch * 8;
            cp16(db + so,              A0h + ga);
            cp16(db + TILE_B + so,     A0l + ga);
            cp16(db + 2 * TILE_B + so, B0h + gb);
            cp16(db + 3 * TILE_B + so, B0l + gb);
        }
        cp_commit();
    };

    float acc[4][4][4];
#pragma unroll
    for (int i = 0; i < 4; i++)
#pragma unroll
        for (int j = 0; j < 4; j++)
#pragma unroll
            for (int v = 0; v < 4; v++) acc[i][j][v] = 0.0f;

    const uint32_t a_l = ((uint32_t)(lane & 15) << 6) + ((uint32_t)(lane >> 4) << 4);
    const uint32_t b_l = ((uint32_t)(lane & 7) << 6) + ((uint32_t)((lane >> 3) & 1) << 4);

    load_tile(0);
    load_tile(1);

    for (int it = 0; it < nIter; ++it) {
        if (it + 1 < nIter) cp_wait<1>(); else cp_wait<0>();
        __syncthreads();

        const uint32_t db = sbase + (uint32_t)(it & 1) * STAGE_B;
#pragma unroll
        for (int ks = 0; ks < 2; ks++) {
            uint32_t ah[4][4], al_[4][4], bh[4][2], bl_[4][2];
#pragma unroll
            for (int fm = 0; fm < 4; fm++) {
                const uint32_t sw = SWZ64(((uint32_t)(wm * 64 + fm * 16) << 6) +
                                          (uint32_t)(ks * 32) + a_l);
                ldsm4(db + sw, ah[fm]);
                ldsm4(db + TILE_B + sw, al_[fm]);
            }
#pragma unroll
            for (int fn = 0; fn < 4; fn++) {
                const uint32_t sw = SWZ64(((uint32_t)(wn * 32 + fn * 8) << 6) +
                                          (uint32_t)(ks * 32) + b_l);
                ldsm2(db + 2 * TILE_B + sw, bh[fn]);
                ldsm2(db + 3 * TILE_B + sw, bl_[fn]);
            }
#pragma unroll
            for (int fm = 0; fm < 4; fm++)
#pragma unroll
                for (int fn = 0; fn < 4; fn++)
                    mma16816(acc[fm][fn], ah[fm], bh[fn]);
#pragma unroll
            for (int fm = 0; fm < 4; fm++)
#pragma unroll
                for (int fn = 0; fn < 4; fn++)
                    mma16816(acc[fm][fn], ah[fm], bl_[fn]);
#pragma unroll
            for (int fm = 0; fm < 4; fm++)
#pragma unroll
                for (int fn = 0; fn < 4; fn++)
                    mma16816(acc[fm][fn], al_[fm], bh[fn]);
        }
        __syncthreads();
        if (it + 2 < nIter) load_tile(it + 2);
    }

    const int er = lane >> 2;
    const int ec = (lane & 3) * 2;
#pragma unroll
    for (int fm = 0; fm < 4; fm++) {
#pragma unroll
        for (int fn = 0; fn < 4; fn++) {
            const int r0 = m0 + wm * 64 + fm * 16 + er;
            const int r1 = r0 + 8;
            const int c  = n0 + wn * 32 + fn * 8 + ec;
            *(float2*)(Of + (size_t)r0 * ldc + c) =
                make_float2(to_tf32(acc[fm][fn][0]), to_tf32(acc[fm][fn][1]));
            *(float2*)(Of + (size_t)r1 * ldc + c) =
                make_float2(to_tf32(acc[fm][fn][2]), to_tf32(acc[fm][fn][3]));
        }
    }
}

// ---------------------------------------------------------------------------
// 128x128 NT GEMM tile, single-term TF32 (pre-rounded operands), SW128.
// ROUND 1: round output to tf32.  ROUND 0: plain fp32 out.
// ---------------------------------------------------------------------------
template <int ROUND>
__device__ __forceinline__ void tf32_core(
    const float* __restrict__ A, int lda,
    const float* __restrict__ B, int ldb,
    int m0, int n0, int nIter,
    float* __restrict__ C, int ldc)
{
    extern __shared__ char smem[];
    const uint32_t sbase = smem_u32(smem);
    const int tid  = threadIdx.x;
    const int lane = tid & 31;
    const int wid  = tid >> 5;
    const int wm   = wid >> 2;
    const int wn   = wid & 3;

    const float* A0 = A + (size_t)m0 * lda;
    const float* B0 = B + (size_t)n0 * ldb;

    auto load_tile = [&](int it) {
        const uint32_t db = sbase + (uint32_t)(it & 1) * PV_STAGE_B;
        const int k0 = it * BK2;
#pragma unroll
        for (int i = 0; i < 4; i++) {
            const int c = tid + i * NTHREADS;
            const int row = c >> 3, ch = c & 7;
            const uint32_t so = SWZ((uint32_t)(row * 128 + ch * 16));
            cp16(db + so,             A0 + (size_t)row * lda + k0 + ch * 4);
            cp16(db + PV_TILE_B + so, B0 + (size_t)row * ldb + k0 + ch * 4);
        }
        cp_commit();
    };

    float acc[4][4][4];
#pragma unroll
    for (int i = 0; i < 4; i++)
#pragma unroll
        for (int j = 0; j < 4; j++)
#pragma unroll
            for (int v = 0; v < 4; v++) acc[i][j][v] = 0.0f;

    load_tile(0);
    load_tile(1);

    const int ar = lane >> 2;
    const int ac = lane & 3;

    for (int it = 0; it < nIter; ++it) {
        if (it + 1 < nIter) cp_wait<1>(); else cp_wait<0>();
        __syncthreads();

        const uint32_t db = sbase + (uint32_t)(it & 1) * PV_STAGE_B;
#pragma unroll
        for (int ks = 0; ks < 4; ks++) {
            const uint32_t c0 = (uint32_t)(ks * 8 + ac) * 4;
            uint32_t a[4][4], bb[4][2];
#pragma unroll
            for (int fm = 0; fm < 4; fm++) {
                const uint32_t r = (uint32_t)(wm * 64 + fm * 16 + ar) * 128;
                a[fm][0] = lds32(db + SWZ(r + c0));
                a[fm][1] = lds32(db + SWZ(r + 1024 + c0));
                a[fm][2] = lds32(db + SWZ(r + c0 + 16));
                a[fm][3] = lds32(db + SWZ(r + 1024 + c0 + 16));
            }
#pragma unroll
            for (int fn = 0; fn < 4; fn++) {
                const uint32_t r = (uint32_t)(wn * 32 + fn * 8 + ar) * 128;
                bb[fn][0] = lds32(db + PV_TILE_B + SWZ(r + c0));
                bb[fn][1] = lds32(db + PV_TILE_B + SWZ(r + c0 + 16));
            }
#pragma unroll
            for (int fm = 0; fm < 4; fm++)
#pragma unroll
                for (int fn = 0; fn < 4; fn++)
                    mma1688t(acc[fm][fn], a[fm], bb[fn]);
        }
        __syncthreads();
        if (it + 2 < nIter) load_tile(it + 2);
    }

    const int er = lane >> 2;
    const int ec = (lane & 3) * 2;
#pragma unroll
    for (int fm = 0; fm < 4; fm++) {
#pragma unroll
        for (int fn = 0; fn < 4; fn++) {
            const int r0 = m0 + wm * 64 + fm * 16 + er;
            const int r1 = r0 + 8;
            const int c  = n0 + wn * 32 + fn * 8 + ec;
            if (ROUND) {
                *(float2*)(C + (size_t)r0 * ldc + c) =
                    make_float2(to_tf32(acc[fm][fn][0]), to_tf32(acc[fm][fn][1]));
                *(float2*)(C + (size_t)r1 * ldc + c) =
                    make_float2(to_tf32(acc[fm][fn][2]), to_tf32(acc[fm][fn][3]));
            } else {
                *(float2*)(C + (size_t)r0 * ldc + c) = make_float2(acc[fm][fn][0], acc[fm][fn][1]);
                *(float2*)(C + (size_t)r1 * ldc + c) = make_float2(acc[fm][fn][2], acc[fm][fn][3]);
            }
        }
    }
}

// ---------------------------------------------------------------------------
// Kernel 0: convert. x -> xt; wv -> wvt (both tf32-rounded fp32).
// ---------------------------------------------------------------------------
#define NX4 (NTOK * DIM / 4)
#define NW4 (DIM * DIM / 4)

__global__ __launch_bounds__(NTHREADS)
void convert_kernel(const float* __restrict__ x, const float* __restrict__ wv)
{
    const int i = blockIdx.x * NTHREADS + threadIdx.x;
    if (i < NX4) {
        const float4 v = ((const float4*)x)[i];
        ((float4*)g_xt)[i] = make_float4(to_tf32(v.x), to_tf32(v.y),
                                         to_tf32(v.z), to_tf32(v.w));
    } else if (i < NX4 + NW4) {
        const int j = i - NX4;
        const float4 v = ((const float4*)wv)[j];
        ((float4*)g_wvt)[j] = make_float4(to_tf32(v.x), to_tf32(v.y),
                                          to_tf32(v.z), to_tf32(v.w));
    }
}

// ---------------------------------------------------------------------------
// Kernel 1: tiled transpose wq, wk -> bf16 hi/lo pairs of W^T.
// ---------------------------------------------------------------------------
__global__ __launch_bounds__(NTHREADS)
void transpose_w_kernel(const float* __restrict__ wq, const float* __restrict__ wk)
{
    __shared__ float t[32][33];
    const float* src = blockIdx.z ? wk : wq;
    __nv_bfloat16* oh = blockIdx.z ? g_wkTh : g_wqTh;
    __nv_bfloat16* ol = blockIdx.z ? g_wkTl : g_wqTl;
    const int tx = threadIdx.x & 31, ty = threadIdx.x >> 5;
    const int c0 = blockIdx.x * 32, r0 = blockIdx.y * 32;
#pragma unroll
    for (int i = 0; i < 4; i++)
        t[ty + i * 8][tx] = src[(size_t)(r0 + ty + i * 8) * DIM + c0 + tx];
    __syncthreads();
#pragma unroll
    for (int i = 0; i < 4; i++) {
        const int d = c0 + ty + i * 8;
        const int e = r0 + tx;
        const float v = t[tx][ty + i * 8];
        const __nv_bfloat16 h = __float2bfloat16(v);
        oh[(size_t)d * DIM + e] = h;
        ol[(size_t)d * DIM + e] = __float2bfloat16(v - __bfloat162float(h));
    }
}

// ---------------------------------------------------------------------------
// Kernel 2: fused V + M.
//   CTA < 384:  V^T = Wv X^T, single-term tf32, out g_vt (tf32-rounded)
//   CTA >= 384: Mrow = Wk^T x Wq^T (3-term bf16), out g_mt (tf32-rounded fp32)
// ---------------------------------------------------------------------------
__global__ __launch_bounds__(NTHREADS, 2)
void vm_kernel()
{
    const int cta = blockIdx.x;
    if (cta < 384) {
        const int mi = cta / 64, ni = cta % 64;
        tf32_core<1>(g_wvt, DIM, g_xt, DIM,
                     mi * 128, ni * 128, DIM / BK2, g_vt, NTOK);
    } else {
        const int c2 = cta - 384;
        const int mi = c2 / 6, ni = c2 % 6;
        gemm_core_m(g_wkTh, g_wkTl, DIM, g_wqTh, g_wqTl, DIM,
                    mi * 128, ni * 128, DIM / BK, g_mt, DIM);
    }
}

// ---------------------------------------------------------------------------
// Kernel 3: Y = X * Mrow^T, single-term TF32, tf32-rounded out. grid (6,64).
// ---------------------------------------------------------------------------
__global__ __launch_bounds__(NTHREADS, 2)
void y_kernel()
{
    tf32_core<1>(g_xt, DIM, g_mt, DIM,
                 blockIdx.y * 128, blockIdx.x * 128, DIM / BK2,
                 g_yt, DIM);
}

// ---------------------------------------------------------------------------
// Kernel 4: scores S = Y X^T, single-term TF32, packed triangle grid (136,4).
// ---------------------------------------------------------------------------
__global__ __launch_bounds__(NTHREADS, 2)
void scores_kernel()
{
    const int t = blockIdx.x;
    int mi = (int)((sqrtf(8.0f * (float)t + 1.0f) - 1.0f) * 0.5f);
    while ((mi + 1) * (mi + 2) / 2 <= t) mi++;
    while (mi * (mi + 1) / 2 > t) mi--;
    const int ni = t - mi * (mi + 1) / 2;

    const int b = blockIdx.y;
    const size_t o = (size_t)b * SEQ * DIM;
    tf32_core<0>(g_yt + o, DIM, g_xt + o, DIM,
                 mi * 128, ni * 128, DIM / BK2,
                 g_s + (size_t)b * SEQ * SEQ, SEQ);
}

// ---------------------------------------------------------------------------
// Kernel 5: causal softmax in place (tf32-rounded probs, bounded I/O).
// ---------------------------------------------------------------------------
__global__ __launch_bounds__(NTHREADS)
void softmax_kernel()
{
    const int q = blockIdx.x, b = blockIdx.y;
    float* row = g_s + ((size_t)b * SEQ + q) * SEQ;
    const int nvalid = q + 1;
    const int zlim = (q & ~127) + 128;
    const int tid = threadIdx.x, lane = tid & 31, wid = tid >> 5;

    __shared__ float sred[8];

    const int e0 = 4 * tid, e1 = 4 * (tid + 256);
    float4 v0 = (e0 < nvalid) ? ((const float4*)row)[tid]
                              : make_float4(0.f, 0.f, 0.f, 0.f);
    float4 v1 = (e1 < nvalid) ? ((const float4*)row)[tid + 256]
                              : make_float4(0.f, 0.f, 0.f, 0.f);

    float f[8] = {v0.x, v0.y, v0.z, v0.w, v1.x, v1.y, v1.z, v1.w};
    int   ei[8] = {e0, e0 + 1, e0 + 2, e0 + 3, e1, e1 + 1, e1 + 2, e1 + 3};

    float mx = -INFINITY;
#pragma unroll
    for (int j = 0; j < 8; j++)
        if (ei[j] < nvalid) mx = fmaxf(mx, f[j]);
#pragma unroll
    for (int o = 16; o > 0; o >>= 1)
        mx = fmaxf(mx, __shfl_xor_sync(0xffffffffu, mx, o));
    if (lane == 0) sred[wid] = mx;
    __syncthreads();
    mx = sred[0];
#pragma unroll
    for (int w = 1; w < 8; w++) mx = fmaxf(mx, sred[w]);

    float sum = 0.0f;
#pragma unroll
    for (int j = 0; j < 8; j++) {
        f[j] = (ei[j] < nvalid) ? expf((f[j] - mx) * SCALE) : 0.0f;
        sum += f[j];
    }
#pragma unroll
    for (int o = 16; o > 0; o >>= 1)
        sum += __shfl_xor_sync(0xffffffffu, sum, o);
    __syncthreads();
    if (lane == 0) sred[wid] = sum;
    __syncthreads();
    sum = 0.0f;
#pragma unroll
    for (int w = 0; w < 8; w++) sum += sred[w];
    const float inv = 1.0f / sum;

    if (e0 < zlim)
        ((float4*)row)[tid] = make_float4(to_tf32(f[0] * inv), to_tf32(f[1] * inv),
                                          to_tf32(f[2] * inv), to_tf32(f[3] * inv));
    if (e1 < zlim)
        ((float4*)row)[tid + 256] = make_float4(to_tf32(f[4] * inv), to_tf32(f[5] * inv),
                                                to_tf32(f[6] * inv), to_tf32(f[7] * inv));
}

// ---------------------------------------------------------------------------
// Kernel 6: O = P V via V^T, single-term tf32, k bounded by causal diagonal.
// ---------------------------------------------------------------------------
__global__ __launch_bounds__(NTHREADS, 2)
void pv_kernel(float* __restrict__ out)
{
    const int b = blockIdx.z;
    const int m0 = blockIdx.y * 128, n0 = blockIdx.x * 128;
    tf32_core<0>(g_s + (size_t)b * SEQ * SEQ, SEQ,
                 g_vt + (size_t)b * SEQ, NTOK,
                 m0, n0, (m0 + 128) / BK2,
                 out + (size_t)b * SEQ * DIM, DIM);
}

// ---------------------------------------------------------------------------
extern "C" void kernel_launch(void* const* d_in, const int* in_sizes, int n_in,
                              void* d_out, int out_size)
{
    const float* x  = (const float*)d_in[0];
    const float* wq = (const float*)d_in[1];
    const float* wk = (const float*)d_in[2];
    const float* wv = (const float*)d_in[3];
    float* out = (float*)d_out;

    cudaFuncSetAttribute(vm_kernel,     cudaFuncAttributeMaxDynamicSharedMemorySize, PV_SMEM);
    cudaFuncSetAttribute(y_kernel,      cudaFuncAttributeMaxDynamicSharedMemorySize, PV_SMEM);
    cudaFuncSetAttribute(scores_kernel, cudaFuncAttributeMaxDynamicSharedMemorySize, PV_SMEM);
    cudaFuncSetAttribute(pv_kernel,     cudaFuncAttributeMaxDynamicSharedMemorySize, PV_SMEM);

    const int ntot = NX4 + NW4;
    convert_kernel<<<(ntot + NTHREADS - 1) / NTHREADS, NTHREADS>>>(x, wv);
    transpose_w_kernel<<<dim3(24, 24, 2), NTHREADS>>>(wq, wk);
    vm_kernel<<<420, NTHREADS, PV_SMEM>>>();
    y_kernel<<<dim3(DIM / 128, NTOK / 128), NTHREADS, PV_SMEM>>>();
    scores_kernel<<<dim3(136, BATCH), NTHREADS, PV_SMEM>>>();
    softmax_kernel<<<dim3(SEQ, BATCH), NTHREADS>>>();
    pv_kernel<<<dim3(DIM / 128, SEQ / 128, BATCH), NTHREADS, PV_SMEM>>>(out);
}

// round 10
// speedup vs baseline: 4.7346x; 1.1261x over previous
#include <cuda_runtime.h>
#include <cuda_bf16.h>
#include <math.h>
#include <stdint.h>

// ---------------------------------------------------------------------------
// Problem constants
// ---------------------------------------------------------------------------
#define BATCH 4
#define SEQ   2048
#define DIM   768
#define NTOK  (BATCH * SEQ)          // 8192
#define NTHREADS 256
#define SCALE 0.03608439182435161f   // 1/sqrt(768)

// bf16 GEMM tiling (M GEMM only): 128x128 tile, K chunk 32 bf16, SW64
#define BK 32
#define TILE_B  8192
#define STAGE_B (4 * TILE_B)         // 32 KB
#define SMEM_BYTES (2 * STAGE_B)     // 64 KB

// tf32 tiling: 128x128 CTA tile, K chunk of 32 fp32 (128B rows, SW128)
#define BK2 32
#define PV_TILE_B  16384
#define PV_STAGE_B (2 * PV_TILE_B)
#define PV_SMEM    (2 * PV_STAGE_B)  // 64 KB

#define SWZ(o)   ((o) ^ ((((uint32_t)(o)) >> 3) & 0x70))   // SW128
#define SWZ64(o) ((o) ^ ((((uint32_t)(o)) >> 3) & 0x30))   // SW64

// ---------------------------------------------------------------------------
// Scratch (__device__ globals; referenced ONLY from device code)
// ---------------------------------------------------------------------------
__device__ __align__(128) float         g_xt[NTOK * DIM];      // x tf32-rounded
__device__ __align__(128) __nv_bfloat16 g_wqTh[DIM * DIM], g_wqTl[DIM * DIM];
__device__ __align__(128) __nv_bfloat16 g_wkTh[DIM * DIM], g_wkTl[DIM * DIM];
__device__ __align__(128) float         g_wvt[DIM * DIM];      // wv tf32-rounded
__device__ __align__(128) float         g_mt[DIM * DIM];       // Mrow tf32-rounded
__device__ __align__(128) float         g_yt[NTOK * DIM];      // Y tf32-rounded
__device__ __align__(128) float         g_vt[DIM * NTOK];      // V^T tf32-rounded
__device__ __align__(128) float         g_s[(size_t)BATCH * SEQ * SEQ];

// ---------------------------------------------------------------------------
// PTX helpers
// ---------------------------------------------------------------------------
__device__ __forceinline__ uint32_t smem_u32(const void* p) {
    uint32_t a;
    asm("{ .reg .u64 t; cvta.to.shared.u64 t, %1; cvt.u32.u64 %0, t; }"
        : "=r"(a) : "l"(p));
    return a;
}
__device__ __forceinline__ void cp16(uint32_t dst, const void* src) {
    asm volatile("cp.async.cg.shared.global [%0], [%1], 16;" :: "r"(dst), "l"(src));
}
__device__ __forceinline__ void cp_commit() {
    asm volatile("cp.async.commit_group;" ::: "memory");
}
template <int N>
__device__ __forceinline__ void cp_wait() {
    asm volatile("cp.async.wait_group %0;" :: "n"(N) : "memory");
}
__device__ __forceinline__ void ldsm4(uint32_t addr, uint32_t* r) {
    asm volatile("ldmatrix.sync.aligned.m8n8.x4.shared.b16 {%0,%1,%2,%3}, [%4];"
                 : "=r"(r[0]), "=r"(r[1]), "=r"(r[2]), "=r"(r[3]) : "r"(addr));
}
__device__ __forceinline__ void ldsm2(uint32_t addr, uint32_t* r) {
    asm volatile("ldmatrix.sync.aligned.m8n8.x2.shared.b16 {%0,%1}, [%2];"
                 : "=r"(r[0]), "=r"(r[1]) : "r"(addr));
}
__device__ __forceinline__ void mma16816(float* d, const uint32_t* a, const uint32_t* b) {
    asm volatile(
        "mma.sync.aligned.m16n8k16.row.col.f32.bf16.bf16.f32 "
        "{%0,%1,%2,%3}, {%4,%5,%6,%7}, {%8,%9}, {%0,%1,%2,%3};"
        : "+f"(d[0]), "+f"(d[1]), "+f"(d[2]), "+f"(d[3])
        : "r"(a[0]), "r"(a[1]), "r"(a[2]), "r"(a[3]), "r"(b[0]), "r"(b[1]));
}
__device__ __forceinline__ void mma1688t(float* d, const uint32_t* a, const uint32_t* b) {
    asm volatile(
        "mma.sync.aligned.m16n8k8.row.col.f32.tf32.tf32.f32 "
        "{%0,%1,%2,%3}, {%4,%5,%6,%7}, {%8,%9}, {%0,%1,%2,%3};"
        : "+f"(d[0]), "+f"(d[1]), "+f"(d[2]), "+f"(d[3])
        : "r"(a[0]), "r"(a[1]), "r"(a[2]), "r"(a[3]), "r"(b[0]), "r"(b[1]));
}
__device__ __forceinline__ float to_tf32(float x) {
    float r;
    asm("cvt.rna.tf32.f32 %0, %1;" : "=f"(r) : "f"(x));
    return r;
}

// ---------------------------------------------------------------------------
// 128x128 NT GEMM tile, split-bf16 3-term, BK=32, SW64.
// Used ONLY for the tiny M GEMM. Epilogue: tf32-rounded fp32 out.
// ---------------------------------------------------------------------------
__device__ __forceinline__ void gemm_core_m(
    const __nv_bfloat16* __restrict__ Ah, const __nv_bfloat16* __restrict__ Al, int lda,
    const __nv_bfloat16* __restrict__ Bh, const __nv_bfloat16* __restrict__ Bl, int ldb,
    int m0, int n0, int nIter,
    float* __restrict__ Of, int ldc)
{
    extern __shared__ char smem[];
    const uint32_t sbase = smem_u32(smem);
    const int tid  = threadIdx.x;
    const int lane = tid & 31;
    const int wid  = tid >> 5;
    const int wm   = wid >> 2;
    const int wn   = wid & 3;

    const __nv_bfloat16* A0h = Ah + (size_t)m0 * lda;
    const __nv_bfloat16* A0l = Al + (size_t)m0 * lda;
    const __nv_bfloat16* B0h = Bh + (size_t)n0 * ldb;
    const __nv_bfloat16* B0l = Bl + (size_t)n0 * ldb;

    auto load_tile = [&](int it) {
        const uint32_t db = sbase + (uint32_t)(it & 1) * STAGE_B;
        const int k0 = it * BK;
#pragma unroll
        for (int i = 0; i < 2; i++) {
            const int c = tid + i * NTHREADS;
            const int row = c >> 2, ch = c & 3;
            const uint32_t so = SWZ64((uint32_t)(row * 64 + ch * 16));
            const size_t ga = (size_t)row * lda + k0 + ch * 8;
            const size_t gb = (size_t)row * ldb + k0 + ch * 8;
            cp16(db + so,              A0h + ga);
            cp16(db + TILE_B + so,     A0l + ga);
            cp16(db + 2 * TILE_B + so, B0h + gb);
            cp16(db + 3 * TILE_B + so, B0l + gb);
        }
        cp_commit();
    };

    float acc[4][4][4];
#pragma unroll
    for (int i = 0; i < 4; i++)
#pragma unroll
        for (int j = 0; j < 4; j++)
#pragma unroll
            for (int v = 0; v < 4; v++) acc[i][j][v] = 0.0f;

    const uint32_t a_l = ((uint32_t)(lane & 15) << 6) + ((uint32_t)(lane >> 4) << 4);
    const uint32_t b_l = ((uint32_t)(lane & 7) << 6) + ((uint32_t)((lane >> 3) & 1) << 4);

    load_tile(0);
    load_tile(1);

    for (int it = 0; it < nIter; ++it) {
        if (it + 1 < nIter) cp_wait<1>(); else cp_wait<0>();
        __syncthreads();

        const uint32_t db = sbase + (uint32_t)(it & 1) * STAGE_B;
#pragma unroll
        for (int ks = 0; ks < 2; ks++) {
            uint32_t ah[4][4], al_[4][4], bh[4][2], bl_[4][2];
#pragma unroll
            for (int fm = 0; fm < 4; fm++) {
                const uint32_t sw = SWZ64(((uint32_t)(wm * 64 + fm * 16) << 6) +
                                          (uint32_t)(ks * 32) + a_l);
                ldsm4(db + sw, ah[fm]);
                ldsm4(db + TILE_B + sw, al_[fm]);
            }
#pragma unroll
            for (int fn = 0; fn < 4; fn++) {
                const uint32_t sw = SWZ64(((uint32_t)(wn * 32 + fn * 8) << 6) +
                                          (uint32_t)(ks * 32) + b_l);
                ldsm2(db + 2 * TILE_B + sw, bh[fn]);
                ldsm2(db + 3 * TILE_B + sw, bl_[fn]);
            }
#pragma unroll
            for (int fm = 0; fm < 4; fm++)
#pragma unroll
                for (int fn = 0; fn < 4; fn++)
                    mma16816(acc[fm][fn], ah[fm], bh[fn]);
#pragma unroll
            for (int fm = 0; fm < 4; fm++)
#pragma unroll
                for (int fn = 0; fn < 4; fn++)
                    mma16816(acc[fm][fn], ah[fm], bl_[fn]);
#pragma unroll
            for (int fm = 0; fm < 4; fm++)
#pragma unroll
                for (int fn = 0; fn < 4; fn++)
                    mma16816(acc[fm][fn], al_[fm], bh[fn]);
        }
        __syncthreads();
        if (it + 2 < nIter) load_tile(it + 2);
    }

    const int er = lane >> 2;
    const int ec = (lane & 3) * 2;
#pragma unroll
    for (int fm = 0; fm < 4; fm++) {
#pragma unroll
        for (int fn = 0; fn < 4; fn++) {
            const int r0 = m0 + wm * 64 + fm * 16 + er;
            const int r1 = r0 + 8;
            const int c  = n0 + wn * 32 + fn * 8 + ec;
            *(float2*)(Of + (size_t)r0 * ldc + c) =
                make_float2(to_tf32(acc[fm][fn][0]), to_tf32(acc[fm][fn][1]));
            *(float2*)(Of + (size_t)r1 * ldc + c) =
                make_float2(to_tf32(acc[fm][fn][2]), to_tf32(acc[fm][fn][3]));
        }
    }
}

// ---------------------------------------------------------------------------
// 128x128 NT GEMM tile, single-term TF32, SW128, ldmatrix fragment loads.
// Key fact: an 8x8 b16 ldmatrix tile == an 8x4 fp32 tile whose lane
// distribution (lane -> row lane/4, word lane%4) is exactly the tf32
// m16n8k8 fragment layout. A frag = 1 ldsm4, B frag = 1 ldsm2.
// ROUND 1: round output to tf32.  ROUND 0: plain fp32 out.
// ---------------------------------------------------------------------------
template <int ROUND>
__device__ __forceinline__ void tf32_core(
    const float* __restrict__ A, int lda,
    const float* __restrict__ B, int ldb,
    int m0, int n0, int nIter,
    float* __restrict__ C, int ldc)
{
    extern __shared__ char smem[];
    const uint32_t sbase = smem_u32(smem);
    const int tid  = threadIdx.x;
    const int lane = tid & 31;
    const int wid  = tid >> 5;
    const int wm   = wid >> 2;
    const int wn   = wid & 3;

    const float* A0 = A + (size_t)m0 * lda;
    const float* B0 = B + (size_t)n0 * ldb;

    auto load_tile = [&](int it) {
        const uint32_t db = sbase + (uint32_t)(it & 1) * PV_STAGE_B;
        const int k0 = it * BK2;
#pragma unroll
        for (int i = 0; i < 4; i++) {
            const int c = tid + i * NTHREADS;
            const int row = c >> 3, ch = c & 7;
            const uint32_t so = SWZ((uint32_t)(row * 128 + ch * 16));
            cp16(db + so,             A0 + (size_t)row * lda + k0 + ch * 4);
            cp16(db + PV_TILE_B + so, B0 + (size_t)row * ldb + k0 + ch * 4);
        }
        cp_commit();
    };

    float acc[4][4][4];
#pragma unroll
    for (int i = 0; i < 4; i++)
#pragma unroll
        for (int j = 0; j < 4; j++)
#pragma unroll
            for (int v = 0; v < 4; v++) acc[i][j][v] = 0.0f;

    // ldmatrix per-lane address components (128B rows):
    // A (ldsm4): lanes 0-7 -> m0 rows (r, col+0), 8-15 -> m1 (r+8, +0),
    //            16-23 -> m2 (r, +16B), 24-31 -> m3 (r+8, +16B)
    // B (ldsm2): lanes 0-7 -> m0 rows (n, +0), 8-15 -> m1 (n, +16B)
    const uint32_t a_l = ((uint32_t)(lane & 15) << 7) + ((uint32_t)(lane >> 4) << 4);
    const uint32_t b_l = ((uint32_t)(lane & 7) << 7) + ((uint32_t)((lane >> 3) & 1) << 4);

    load_tile(0);
    load_tile(1);

    for (int it = 0; it < nIter; ++it) {
        if (it + 1 < nIter) cp_wait<1>(); else cp_wait<0>();
        __syncthreads();

        const uint32_t db = sbase + (uint32_t)(it & 1) * PV_STAGE_B;
#pragma unroll
        for (int ks = 0; ks < 4; ks++) {
            uint32_t a[4][4], bb[4][2];
#pragma unroll
            for (int fm = 0; fm < 4; fm++) {
                const uint32_t sw = SWZ(((uint32_t)(wm * 64 + fm * 16) << 7) +
                                        (uint32_t)(ks * 32) + a_l);
                ldsm4(db + sw, a[fm]);
            }
#pragma unroll
            for (int fn = 0; fn < 4; fn++) {
                const uint32_t sw = SWZ(((uint32_t)(wn * 32 + fn * 8) << 7) +
                                        (uint32_t)(ks * 32) + b_l);
                ldsm2(db + PV_TILE_B + sw, bb[fn]);
            }
#pragma unroll
            for (int fm = 0; fm < 4; fm++)
#pragma unroll
                for (int fn = 0; fn < 4; fn++)
                    mma1688t(acc[fm][fn], a[fm], bb[fn]);
        }
        __syncthreads();
        if (it + 2 < nIter) load_tile(it + 2);
    }

    const int er = lane >> 2;
    const int ec = (lane & 3) * 2;
#pragma unroll
    for (int fm = 0; fm < 4; fm++) {
#pragma unroll
        for (int fn = 0; fn < 4; fn++) {
            const int r0 = m0 + wm * 64 + fm * 16 + er;
            const int r1 = r0 + 8;
            const int c  = n0 + wn * 32 + fn * 8 + ec;
            if (ROUND) {
                *(float2*)(C + (size_t)r0 * ldc + c) =
                    make_float2(to_tf32(acc[fm][fn][0]), to_tf32(acc[fm][fn][1]));
                *(float2*)(C + (size_t)r1 * ldc + c) =
                    make_float2(to_tf32(acc[fm][fn][2]), to_tf32(acc[fm][fn][3]));
            } else {
                *(float2*)(C + (size_t)r0 * ldc + c) = make_float2(acc[fm][fn][0], acc[fm][fn][1]);
                *(float2*)(C + (size_t)r1 * ldc + c) = make_float2(acc[fm][fn][2], acc[fm][fn][3]);
            }
        }
    }
}

// ---------------------------------------------------------------------------
// Kernel 0: convert. x -> xt; wv -> wvt (both tf32-rounded fp32).
// ---------------------------------------------------------------------------
#define NX4 (NTOK * DIM / 4)
#define NW4 (DIM * DIM / 4)

__global__ __launch_bounds__(NTHREADS)
void convert_kernel(const float* __restrict__ x, const float* __restrict__ wv)
{
    const int i = blockIdx.x * NTHREADS + threadIdx.x;
    if (i < NX4) {
        const float4 v = ((const float4*)x)[i];
        ((float4*)g_xt)[i] = make_float4(to_tf32(v.x), to_tf32(v.y),
                                         to_tf32(v.z), to_tf32(v.w));
    } else if (i < NX4 + NW4) {
        const int j = i - NX4;
        const float4 v = ((const float4*)wv)[j];
        ((float4*)g_wvt)[j] = make_float4(to_tf32(v.x), to_tf32(v.y),
                                          to_tf32(v.z), to_tf32(v.w));
    }
}

// ---------------------------------------------------------------------------
// Kernel 1: tiled transpose wq, wk -> bf16 hi/lo pairs of W^T.
// ---------------------------------------------------------------------------
__global__ __launch_bounds__(NTHREADS)
void transpose_w_kernel(const float* __restrict__ wq, const float* __restrict__ wk)
{
    __shared__ float t[32][33];
    const float* src = blockIdx.z ? wk : wq;
    __nv_bfloat16* oh = blockIdx.z ? g_wkTh : g_wqTh;
    __nv_bfloat16* ol = blockIdx.z ? g_wkTl : g_wqTl;
    const int tx = threadIdx.x & 31, ty = threadIdx.x >> 5;
    const int c0 = blockIdx.x * 32, r0 = blockIdx.y * 32;
#pragma unroll
    for (int i = 0; i < 4; i++)
        t[ty + i * 8][tx] = src[(size_t)(r0 + ty + i * 8) * DIM + c0 + tx];
    __syncthreads();
#pragma unroll
    for (int i = 0; i < 4; i++) {
        const int d = c0 + ty + i * 8;
        const int e = r0 + tx;
        const float v = t[tx][ty + i * 8];
        const __nv_bfloat16 h = __float2bfloat16(v);
        oh[(size_t)d * DIM + e] = h;
        ol[(size_t)d * DIM + e] = __float2bfloat16(v - __bfloat162float(h));
    }
}

// ---------------------------------------------------------------------------
// Kernel 2: fused V + M.
//   CTA < 384:  V^T = Wv X^T, single-term tf32, out g_vt (tf32-rounded)
//   CTA >= 384: Mrow = Wk^T x Wq^T (3-term bf16), out g_mt (tf32-rounded fp32)
// ---------------------------------------------------------------------------
__global__ __launch_bounds__(NTHREADS, 2)
void vm_kernel()
{
    const int cta = blockIdx.x;
    if (cta < 384) {
        const int mi = cta / 64, ni = cta % 64;
        tf32_core<1>(g_wvt, DIM, g_xt, DIM,
                     mi * 128, ni * 128, DIM / BK2, g_vt, NTOK);
    } else {
        const int c2 = cta - 384;
        const int mi = c2 / 6, ni = c2 % 6;
        gemm_core_m(g_wkTh, g_wkTl, DIM, g_wqTh, g_wqTl, DIM,
                    mi * 128, ni * 128, DIM / BK, g_mt, DIM);
    }
}

// ---------------------------------------------------------------------------
// Kernel 3: Y = X * Mrow^T, single-term TF32, tf32-rounded out. grid (6,64).
// ---------------------------------------------------------------------------
__global__ __launch_bounds__(NTHREADS, 2)
void y_kernel()
{
    tf32_core<1>(g_xt, DIM, g_mt, DIM,
                 blockIdx.y * 128, blockIdx.x * 128, DIM / BK2,
                 g_yt, DIM);
}

// ---------------------------------------------------------------------------
// Kernel 4: scores S = Y X^T, single-term TF32, packed triangle grid (136,4).
// ---------------------------------------------------------------------------
__global__ __launch_bounds__(NTHREADS, 2)
void scores_kernel()
{
    const int t = blockIdx.x;
    int mi = (int)((sqrtf(8.0f * (float)t + 1.0f) - 1.0f) * 0.5f);
    while ((mi + 1) * (mi + 2) / 2 <= t) mi++;
    while (mi * (mi + 1) / 2 > t) mi--;
    const int ni = t - mi * (mi + 1) / 2;

    const int b = blockIdx.y;
    const size_t o = (size_t)b * SEQ * DIM;
    tf32_core<0>(g_yt + o, DIM, g_xt + o, DIM,
                 mi * 128, ni * 128, DIM / BK2,
                 g_s + (size_t)b * SEQ * SEQ, SEQ);
}

// ---------------------------------------------------------------------------
// Kernel 5: causal softmax in place (tf32-rounded probs, bounded I/O).
// ---------------------------------------------------------------------------
__global__ __launch_bounds__(NTHREADS)
void softmax_kernel()
{
    const int q = blockIdx.x, b = blockIdx.y;
    float* row = g_s + ((size_t)b * SEQ + q) * SEQ;
    const int nvalid = q + 1;
    const int zlim = (q & ~127) + 128;
    const int tid = threadIdx.x, lane = tid & 31, wid = tid >> 5;

    __shared__ float sred[8];

    const int e0 = 4 * tid, e1 = 4 * (tid + 256);
    float4 v0 = (e0 < nvalid) ? ((const float4*)row)[tid]
                              : make_float4(0.f, 0.f, 0.f, 0.f);
    float4 v1 = (e1 < nvalid) ? ((const float4*)row)[tid + 256]
                              : make_float4(0.f, 0.f, 0.f, 0.f);

    float f[8] = {v0.x, v0.y, v0.z, v0.w, v1.x, v1.y, v1.z, v1.w};
    int   ei[8] = {e0, e0 + 1, e0 + 2, e0 + 3, e1, e1 + 1, e1 + 2, e1 + 3};

    float mx = -INFINITY;
#pragma unroll
    for (int j = 0; j < 8; j++)
        if (ei[j] < nvalid) mx = fmaxf(mx, f[j]);
#pragma unroll
    for (int o = 16; o > 0; o >>= 1)
        mx = fmaxf(mx, __shfl_xor_sync(0xffffffffu, mx, o));
    if (lane == 0) sred[wid] = mx;
    __syncthreads();
    mx = sred[0];
#pragma unroll
    for (int w = 1; w < 8; w++) mx = fmaxf(mx, sred[w]);

    float sum = 0.0f;
#pragma unroll
    for (int j = 0; j < 8; j++) {
        f[j] = (ei[j] < nvalid) ? expf((f[j] - mx) * SCALE) : 0.0f;
        sum += f[j];
    }
#pragma unroll
    for (int o = 16; o > 0; o >>= 1)
        sum += __shfl_xor_sync(0xffffffffu, sum, o);
    __syncthreads();
    if (lane == 0) sred[wid] = sum;
    __syncthreads();
    sum = 0.0f;
#pragma unroll
    for (int w = 0; w < 8; w++) sum += sred[w];
    const float inv = 1.0f / sum;

    if (e0 < zlim)
        ((float4*)row)[tid] = make_float4(to_tf32(f[0] * inv), to_tf32(f[1] * inv),
                                          to_tf32(f[2] * inv), to_tf32(f[3] * inv));
    if (e1 < zlim)
        ((float4*)row)[tid + 256] = make_float4(to_tf32(f[4] * inv), to_tf32(f[5] * inv),
                                                to_tf32(f[6] * inv), to_tf32(f[7] * inv));
}

// ---------------------------------------------------------------------------
// Kernel 6: O = P V via V^T, single-term tf32, k bounded by causal diagonal.
// ---------------------------------------------------------------------------
__global__ __launch_bounds__(NTHREADS, 2)
void pv_kernel(float* __restrict__ out)
{
    const int b = blockIdx.z;
    const int m0 = blockIdx.y * 128, n0 = blockIdx.x * 128;
    tf32_core<0>(g_s + (size_t)b * SEQ * SEQ, SEQ,
                 g_vt + (size_t)b * SEQ, NTOK,
                 m0, n0, (m0 + 128) / BK2,
                 out + (size_t)b * SEQ * DIM, DIM);
}

// ---------------------------------------------------------------------------
extern "C" void kernel_launch(void* const* d_in, const int* in_sizes, int n_in,
                              void* d_out, int out_size)
{
    const float* x  = (const float*)d_in[0];
    const float* wq = (const float*)d_in[1];
    const float* wk = (const float*)d_in[2];
    const float* wv = (const float*)d_in[3];
    float* out = (float*)d_out;

    cudaFuncSetAttribute(vm_kernel,     cudaFuncAttributeMaxDynamicSharedMemorySize, PV_SMEM);
    cudaFuncSetAttribute(y_kernel,      cudaFuncAttributeMaxDynamicSharedMemorySize, PV_SMEM);
    cudaFuncSetAttribute(scores_kernel, cudaFuncAttributeMaxDynamicSharedMemorySize, PV_SMEM);
    cudaFuncSetAttribute(pv_kernel,     cudaFuncAttributeMaxDynamicSharedMemorySize, PV_SMEM);

    const int ntot = NX4 + NW4;
    convert_kernel<<<(ntot + NTHREADS - 1) / NTHREADS, NTHREADS>>>(x, wv);
    transpose_w_kernel<<<dim3(24, 24, 2), NTHREADS>>>(wq, wk);
    vm_kernel<<<420, NTHREADS, PV_SMEM>>>();
    y_kernel<<<dim3(DIM / 128, NTOK / 128), NTHREADS, PV_SMEM>>>();
    scores_kernel<<<dim3(136, BATCH), NTHREADS, PV_SMEM>>>();
    softmax_kernel<<<dim3(SEQ, BATCH), NTHREADS>>>();
    pv_kernel<<<dim3(DIM / 128, SEQ / 128, BATCH), NTHREADS, PV_SMEM>>>(out);
}